// round 3
// baseline (speedup 1.0000x reference)
#include <cuda_runtime.h>
#include <math.h>

#define NN 10000
#define EE 160000
#define MM (EE + NN)   // 170000 edges incl self loops
#define FD 128
#define BB 4
#define ROWS (BB * NN) // 40000

// ------------------------- scratch (device globals; no allocation) -------------------------
// slots: 0=xl, 1=xr, 2=F, 3=Z, 4=HR
__device__ float g_buf[5][(size_t)ROWS * FD];
__device__ int   g_deg[NN];
__device__ int   g_rowptr[NN + 1];
__device__ int   g_cursor[NN];
__device__ int   g_csrc[MM];

// ------------------------- CSR build -------------------------
__global__ void init_deg_kernel() {
    int i = blockIdx.x * 256 + threadIdx.x;
    if (i < NN) g_deg[i] = 0;
}

// edge_index is int32 on device (JAX default x64-disabled coerces int64->int32).
__global__ void count_deg_kernel(const int* __restrict__ ei) {
    int m = blockIdx.x * 256 + threadIdx.x;
    if (m >= MM) return;
    int d = (m < EE) ? ei[EE + m] : (m - EE);
    if ((unsigned)d < NN) atomicAdd(&g_deg[d], 1);
}

__global__ void scan_kernel() {
    __shared__ int part[1024];
    int tid = threadIdx.x;
    const int CH = 10;                  // 1024*10 >= NN
    int base = tid * CH;
    int loc[CH];
    int s = 0;
#pragma unroll
    for (int i = 0; i < CH; i++) {
        int v = (base + i < NN) ? g_deg[base + i] : 0;
        loc[i] = s; s += v;
    }
    part[tid] = s;
    __syncthreads();
    for (int off = 1; off < 1024; off <<= 1) {
        int add = (tid >= off) ? part[tid - off] : 0;
        __syncthreads();
        part[tid] += add;
        __syncthreads();
    }
    int pre = (tid > 0) ? part[tid - 1] : 0;
#pragma unroll
    for (int i = 0; i < CH; i++) {
        if (base + i < NN) {
            int r = pre + loc[i];
            g_rowptr[base + i] = r;
            g_cursor[base + i] = r;
        }
    }
    if (tid == 1023) g_rowptr[NN] = part[1023];
}

__global__ void scatter_csr_kernel(const int* __restrict__ ei) {
    int m = blockIdx.x * 256 + threadIdx.x;
    if (m >= MM) return;
    int s, d;
    if (m < EE) { s = ei[m]; d = ei[EE + m]; }
    else        { s = d = m - EE; }
    if ((unsigned)d >= NN || (unsigned)s >= NN) return;
    int pos = atomicAdd(&g_cursor[d], 1);
    if (pos < MM) g_csrc[pos] = s;
}

// ------------------------- GEMM (static shared, FFMA) -------------------------
// C[r, o] = sum_f A(f) * W[o, f] (+bias). Tile: 64 rows x 128 cols, 256 threads.
// NPH=1: A only, W row length 128. NPH=2: phase0 A1 w/ W[:,0:128], phase1 A2 w/ W[:,128:256].
// Buffer IDs: >=0 -> g_buf[id]; -1 -> external pointer param.
// MODE 0: out = pre                 (xl / xr projections)
// MODE 1: out = sigmoid(pre)                          -> Z (buf3)
// MODE 2: out = sigmoid(pre) * H                      -> H*R (buf4)
// MODE 3: out = Z*H + (1-Z)*tanh(pre)                 -> final (Z from buf3)
template<int NPH, int MODE, int A1ID, int A2ID, int OUTID>
__global__ __launch_bounds__(256) void gemm_kernel(
    const float* __restrict__ e1,   // external A pointer (X or H) when A1ID/A2ID == -1
    const float* __restrict__ e2,   // external aux pointer (H) for MODE 2/3
    const float* __restrict__ W, const float* __restrict__ bias,
    float* __restrict__ outp)       // external out when OUTID == -1
{
    __shared__ float AsT[128 * 64];   // k-major A tile, 32KB
    __shared__ float Ws [32 * 128];   // one 32-k chunk of W, k-major, 16KB

    const float* A1 = (A1ID >= 0) ? g_buf[A1ID] : e1;
    const float* A2 = (A2ID >= 0) ? g_buf[A2ID] : e1;
    float* out      = (OUTID >= 0) ? g_buf[OUTID] : outp;

    const int tid = threadIdx.x;
    const int rowBase = blockIdx.x * 64;
    const int tx = tid & 15;    // 16 col groups of 8
    const int ty = tid >> 4;    // 16 row groups of 4
    const int c0 = tx * 8;
    const int r0 = ty * 4;
    const int KW = NPH * 128;   // W row stride

    float acc[4][8];
#pragma unroll
    for (int r = 0; r < 4; r++)
#pragma unroll
        for (int j = 0; j < 8; j++) acc[r][j] = 0.f;

#pragma unroll
    for (int ph = 0; ph < NPH; ph++) {
        const float* A = (ph == 0) ? A1 : A2;
        __syncthreads();   // previous compute done with AsT
        // load full A tile transposed: AsT[k][row]   (64 rows x 128 k)
        for (int idx = tid; idx < 64 * 32; idx += 256) {
            int row = idx & 63, kg = idx >> 6;   // kg: 0..31
            float4 v = *(const float4*)(A + (size_t)(rowBase + row) * 128 + kg * 4);
            AsT[(kg * 4 + 0) * 64 + row] = v.x;
            AsT[(kg * 4 + 1) * 64 + row] = v.y;
            AsT[(kg * 4 + 2) * 64 + row] = v.z;
            AsT[(kg * 4 + 3) * 64 + row] = v.w;
        }
#pragma unroll
        for (int kc = 0; kc < 4; kc++) {
            if (kc > 0) __syncthreads();  // previous compute done with Ws
            // load W chunk transposed: Ws[k2][c], k2 in 0..31
            for (int idx = tid; idx < 128 * 8; idx += 256) {
                int c = idx & 127, kg = idx >> 7;
                float4 v = *(const float4*)(W + (size_t)c * KW + ph * 128 + kc * 32 + kg * 4);
                Ws[(kg * 4 + 0) * 128 + c] = v.x;
                Ws[(kg * 4 + 1) * 128 + c] = v.y;
                Ws[(kg * 4 + 2) * 128 + c] = v.z;
                Ws[(kg * 4 + 3) * 128 + c] = v.w;
            }
            __syncthreads();
#pragma unroll
            for (int k2 = 0; k2 < 32; k2++) {
                int k = kc * 32 + k2;
                float4 av = *(const float4*)&AsT[k * 64 + r0];
                float4 w0 = *(const float4*)&Ws[k2 * 128 + c0];
                float4 w1 = *(const float4*)&Ws[k2 * 128 + c0 + 4];
#define GEMM_STEP(r, a) \
                acc[r][0] += (a) * w0.x; acc[r][1] += (a) * w0.y; \
                acc[r][2] += (a) * w0.z; acc[r][3] += (a) * w0.w; \
                acc[r][4] += (a) * w1.x; acc[r][5] += (a) * w1.y; \
                acc[r][6] += (a) * w1.z; acc[r][7] += (a) * w1.w;
                GEMM_STEP(0, av.x)
                GEMM_STEP(1, av.y)
                GEMM_STEP(2, av.z)
                GEMM_STEP(3, av.w)
#undef GEMM_STEP
            }
        }
    }

    // epilogue
#pragma unroll
    for (int r = 0; r < 4; r++) {
        size_t gbase = (size_t)(rowBase + r0 + r) * 128 + c0;
        float res[8];
#pragma unroll
        for (int j = 0; j < 8; j++) {
            float pre = acc[r][j] + bias[c0 + j];
            float v;
            if (MODE == 0) {
                v = pre;
            } else if (MODE == 1) {
                v = 1.f / (1.f + __expf(-pre));
            } else if (MODE == 2) {
                v = (1.f / (1.f + __expf(-pre))) * e2[gbase + j];
            } else {
                float z = g_buf[3][gbase + j];
                v = z * e2[gbase + j] + (1.f - z) * tanhf(pre);
            }
            res[j] = v;
        }
        *(float4*)&out[gbase]     = make_float4(res[0], res[1], res[2], res[3]);
        *(float4*)&out[gbase + 4] = make_float4(res[4], res[5], res[6], res[7]);
    }
}

// ------------------------- fused GATv2 edge phase -------------------------
// One block per (dst node, batch): gather src rows to smem once, compute e,
// chunked online softmax, accumulate messages. F = relu(agg + bias) -> g_buf[2].
// xl = g_buf[0], xr = g_buf[1].
#define CHUNK 64
__global__ __launch_bounds__(128) void gat_agg_kernel(
    const float* __restrict__ att, const float* __restrict__ bias)
{
    const int d = blockIdx.x;
    const int b = blockIdx.y;
    const int tid = threadIdx.x;
    const int lane = tid & 31;
    const int wid = tid >> 5;

    const float* __restrict__ xl = g_buf[0];
    const float* __restrict__ xr = g_buf[1];
    float* __restrict__ Fout = g_buf[2];

    __shared__ float sh_xl[CHUNK][FD];
    __shared__ float sh_w[CHUNK];
    __shared__ int   sh_s[CHUNK];
    __shared__ float sh_xr[FD];
    __shared__ float sh_at[FD];
    __shared__ float red[4];

    const int start = g_rowptr[d];
    const int end   = g_rowptr[d + 1];
    const size_t nb = ((size_t)b * NN + d) * FD;

    sh_xr[tid] = xr[nb + tid];
    sh_at[tid] = att[tid];

    float m_run = -1e30f, denom = 0.f, acc = 0.f;
    __syncthreads();

    for (int cs = start; cs < end; cs += CHUNK) {
        int cn = min(CHUNK, end - cs);
        for (int i = tid; i < cn; i += 128) sh_s[i] = g_csrc[cs + i];
        __syncthreads();
#pragma unroll 4
        for (int i = 0; i < cn; i++)
            sh_xl[i][tid] = xl[((size_t)b * NN + sh_s[i]) * FD + tid];
        __syncthreads();
        // e_i = sum_f lrelu(xl_s[f] + xr_d[f]) * att[f]  (warp per edge)
        for (int i = wid; i < cn; i += 4) {
            float p = 0.f;
#pragma unroll
            for (int q = 0; q < 4; q++) {
                int f = lane + 32 * q;
                float v = sh_xl[i][f] + sh_xr[f];
                v = (v > 0.f) ? v : 0.2f * v;
                p += v * sh_at[f];
            }
#pragma unroll
            for (int o = 16; o > 0; o >>= 1) p += __shfl_xor_sync(0xffffffffu, p, o);
            if (lane == 0) sh_w[i] = p;
        }
        __syncthreads();
        // chunk max
        float cm = -1e30f;
        for (int i = tid; i < cn; i += 128) cm = fmaxf(cm, sh_w[i]);
#pragma unroll
        for (int o = 16; o > 0; o >>= 1) cm = fmaxf(cm, __shfl_xor_sync(0xffffffffu, cm, o));
        if (lane == 0) red[wid] = cm;
        __syncthreads();
        float bm = fmaxf(fmaxf(red[0], red[1]), fmaxf(red[2], red[3]));
        float m_new = fmaxf(m_run, bm);
        float rescale = __expf(m_run - m_new);
        denom *= rescale;
        acc   *= rescale;
        __syncthreads();  // everyone done reading red
        // exp + chunk sum
        float csum = 0.f;
        for (int i = tid; i < cn; i += 128) {
            float w = __expf(sh_w[i] - m_new);
            sh_w[i] = w;
            csum += w;
        }
#pragma unroll
        for (int o = 16; o > 0; o >>= 1) csum += __shfl_xor_sync(0xffffffffu, csum, o);
        if (lane == 0) red[wid] = csum;
        __syncthreads();
        denom += red[0] + red[1] + red[2] + red[3];
        // accumulate messages
#pragma unroll 4
        for (int i = 0; i < cn; i++) acc += sh_w[i] * sh_xl[i][tid];
        m_run = m_new;
        __syncthreads();  // before next chunk overwrites smem
    }

    float r = acc / denom + bias[tid];
    Fout[nb + tid] = fmaxf(r, 0.f);
}

// ------------------------- launch -------------------------
extern "C" void kernel_launch(void* const* d_in, const int* in_sizes, int n_in,
                              void* d_out, int out_size)
{
    (void)in_sizes; (void)n_in; (void)out_size;
    const float* X  = (const float*)d_in[0];
    const int*   EI = (const int*)d_in[1];   // int32 (JAX x64 disabled)
    const float* H  = (const float*)d_in[2];

    // per-gate params: Wl, bl, Wr, br, att, bias, Wlin, blin  (z@3, r@11, h@19)
    const float* p[24];
    for (int i = 0; i < 24; i++) p[i] = (const float*)d_in[3 + i];
    const float **gz = p, **gr = p + 8, **gh = p + 16;

    // CSR build (once; shared by all gates)
    init_deg_kernel<<<(NN + 255) / 256, 256>>>();
    count_deg_kernel<<<(MM + 255) / 256, 256>>>(EI);
    scan_kernel<<<1, 1024>>>();
    scatter_csr_kernel<<<(MM + 255) / 256, 256>>>(EI);

    const int GB = ROWS / 64;   // 625 blocks
    dim3 aggGrid(NN, BB);

    // ---- gate z ----
    gemm_kernel<1,0,-1,-1,0><<<GB, 256>>>(X, nullptr, gz[0], gz[1], nullptr);  // xl
    gemm_kernel<1,0,-1,-1,1><<<GB, 256>>>(X, nullptr, gz[2], gz[3], nullptr);  // xr
    gat_agg_kernel<<<aggGrid, 128>>>(gz[4], gz[5]);                            // F
    gemm_kernel<2,1, 2,-1,3><<<GB, 256>>>(H, nullptr, gz[6], gz[7], nullptr);  // Z = sigmoid([F,H]Wlin)

    // ---- gate r ----
    gemm_kernel<1,0,-1,-1,0><<<GB, 256>>>(X, nullptr, gr[0], gr[1], nullptr);
    gemm_kernel<1,0,-1,-1,1><<<GB, 256>>>(X, nullptr, gr[2], gr[3], nullptr);
    gat_agg_kernel<<<aggGrid, 128>>>(gr[4], gr[5]);
    gemm_kernel<2,2, 2,-1,4><<<GB, 256>>>(H, H, gr[6], gr[7], nullptr);        // HR = sigmoid(.)*H

    // ---- gate h ----
    gemm_kernel<1,0,-1,-1,0><<<GB, 256>>>(X, nullptr, gh[0], gh[1], nullptr);
    gemm_kernel<1,0,-1,-1,1><<<GB, 256>>>(X, nullptr, gh[2], gh[3], nullptr);
    gat_agg_kernel<<<aggGrid, 128>>>(gh[4], gh[5]);
    gemm_kernel<2,3, 2, 4,-1><<<GB, 256>>>(nullptr, H, gh[6], gh[7], (float*)d_out); // out = Z*H+(1-Z)*tanh(.)
}

// round 4
// speedup vs baseline: 1.4953x; 1.4953x over previous
#include <cuda_runtime.h>
#include <math.h>
#include <stdint.h>

#define NN 10000
#define EE 160000
#define MM (EE + NN)   // 170000 edges incl self loops
#define FD 128
#define BB 4
#define ROWS (BB * NN) // 40000

// ------------------------- scratch (device globals; no allocation) -------------------------
// slots: 0=xl, 1=xr, 2=F, 3=Z, 4=HR
__device__ float g_buf[5][(size_t)ROWS * FD];
__device__ int   g_deg[NN];
__device__ int   g_rowptr[NN + 1];
__device__ int   g_cursor[NN];
__device__ int   g_csrc[MM];

// ------------------------- CSR build -------------------------
__global__ void init_deg_kernel() {
    int i = blockIdx.x * 256 + threadIdx.x;
    if (i < NN) g_deg[i] = 0;
}

// edge_index is int32 on device (JAX default x64-disabled coerces int64->int32).
__global__ void count_deg_kernel(const int* __restrict__ ei) {
    int m = blockIdx.x * 256 + threadIdx.x;
    if (m >= MM) return;
    int d = (m < EE) ? ei[EE + m] : (m - EE);
    if ((unsigned)d < NN) atomicAdd(&g_deg[d], 1);
}

__global__ void scan_kernel() {
    __shared__ int part[1024];
    int tid = threadIdx.x;
    const int CH = 10;
    int base = tid * CH;
    int loc[CH];
    int s = 0;
#pragma unroll
    for (int i = 0; i < CH; i++) {
        int v = (base + i < NN) ? g_deg[base + i] : 0;
        loc[i] = s; s += v;
    }
    part[tid] = s;
    __syncthreads();
    for (int off = 1; off < 1024; off <<= 1) {
        int add = (tid >= off) ? part[tid - off] : 0;
        __syncthreads();
        part[tid] += add;
        __syncthreads();
    }
    int pre = (tid > 0) ? part[tid - 1] : 0;
#pragma unroll
    for (int i = 0; i < CH; i++) {
        if (base + i < NN) {
            int r = pre + loc[i];
            g_rowptr[base + i] = r;
            g_cursor[base + i] = r;
        }
    }
    if (tid == 1023) g_rowptr[NN] = part[1023];
}

__global__ void scatter_csr_kernel(const int* __restrict__ ei) {
    int m = blockIdx.x * 256 + threadIdx.x;
    if (m >= MM) return;
    int s, d;
    if (m < EE) { s = ei[m]; d = ei[EE + m]; }
    else        { s = d = m - EE; }
    if ((unsigned)d >= NN || (unsigned)s >= NN) return;
    int pos = atomicAdd(&g_cursor[d], 1);
    if (pos < MM) g_csrc[pos] = s;
}

// ------------------------- tf32 tensor-core GEMM core -------------------------
// C[r,o] = sum_f A(f) * W[o,f] (+bias, +fused epilogue).
// Block tile 128x128, 256 threads = 8 warps (4 in m, 2 in n), warp tile m32 x n64.
// mma.sync.m16n8k8 tf32. Inputs rounded to tf32 (RNA) when staged to smem.
// MODE 0: out = pre
// MODE 1: out = sigmoid(pre)
// MODE 2: out = sigmoid(pre) * aux
// MODE 3: out = zbuf*aux + (1-zbuf)*tanh(pre)

__device__ __forceinline__ float to_tf32(float x) {
    uint32_t u;
    asm("cvt.rna.tf32.f32 %0, %1;" : "=r"(u) : "f"(x));
    return __uint_as_float(u);
}

template<int NPH, int MODE>
__device__ __forceinline__ void gemm_core(
    const float* __restrict__ A1, const float* __restrict__ A2,
    const float* __restrict__ W,  const float* __restrict__ bias,
    const float* __restrict__ aux, const float* __restrict__ zbuf,
    float* __restrict__ out)
{
    __shared__ float As[128 * 36];   // rows 0..127, k 0..31, stride 36 (conflict-free frags)
    __shared__ float Bs[32 * 136];   // k 0..31,   n 0..127, stride 136 (conflict-free frags)

    const int tid  = threadIdx.x;
    const int lane = tid & 31;
    const int w    = tid >> 5;
    const int wm   = w & 3;          // 4 warps in m
    const int wn   = w >> 2;         // 2 warps in n
    const int lr   = lane >> 2;      // 0..7
    const int lc   = lane & 3;       // 0..3
    const int rowBase = blockIdx.x * 128;
    const int KW = NPH * 128;        // W row stride

    float d[2][8][4];
#pragma unroll
    for (int mi = 0; mi < 2; mi++)
#pragma unroll
        for (int ni = 0; ni < 8; ni++)
#pragma unroll
            for (int q = 0; q < 4; q++) d[mi][ni][q] = 0.f;

#pragma unroll
    for (int ph = 0; ph < NPH; ph++) {
        const float* A = (ph == 0) ? A1 : A2;
#pragma unroll
        for (int kc = 0; kc < 4; kc++) {
            __syncthreads();
            // stage A chunk: 128 rows x 32 k (as tf32)
#pragma unroll
            for (int i = 0; i < 4; i++) {
                int idx = tid + i * 256;
                int row = idx >> 3, kg = idx & 7;
                int gr = rowBase + row;
                if (gr >= ROWS) gr = ROWS - 1;        // clamp tail (stores guarded)
                float4 v = *(const float4*)(A + (size_t)gr * 128 + kc * 32 + kg * 4);
                *(float4*)&As[row * 36 + kg * 4] =
                    make_float4(to_tf32(v.x), to_tf32(v.y), to_tf32(v.z), to_tf32(v.w));
            }
            // stage B chunk transposed: Bs[k][n] = W[n][ph*128 + kc*32 + k]
#pragma unroll
            for (int i = 0; i < 4; i++) {
                int idx = tid + i * 256;
                int n = idx & 127, kg = idx >> 7;
                float4 v = *(const float4*)(W + (size_t)n * KW + ph * 128 + kc * 32 + kg * 4);
                Bs[(kg * 4 + 0) * 136 + n] = to_tf32(v.x);
                Bs[(kg * 4 + 1) * 136 + n] = to_tf32(v.y);
                Bs[(kg * 4 + 2) * 136 + n] = to_tf32(v.z);
                Bs[(kg * 4 + 3) * 136 + n] = to_tf32(v.w);
            }
            __syncthreads();

#pragma unroll
            for (int ks = 0; ks < 4; ks++) {
                uint32_t a[2][4], b[8][2];
#pragma unroll
                for (int mi = 0; mi < 2; mi++) {
                    int r = wm * 32 + mi * 16 + lr;
                    a[mi][0] = __float_as_uint(As[(r    ) * 36 + ks * 8 + lc    ]);
                    a[mi][1] = __float_as_uint(As[(r + 8) * 36 + ks * 8 + lc    ]);
                    a[mi][2] = __float_as_uint(As[(r    ) * 36 + ks * 8 + lc + 4]);
                    a[mi][3] = __float_as_uint(As[(r + 8) * 36 + ks * 8 + lc + 4]);
                }
#pragma unroll
                for (int ni = 0; ni < 8; ni++) {
                    int n = wn * 64 + ni * 8 + lr;
                    b[ni][0] = __float_as_uint(Bs[(ks * 8 + lc    ) * 136 + n]);
                    b[ni][1] = __float_as_uint(Bs[(ks * 8 + lc + 4) * 136 + n]);
                }
#pragma unroll
                for (int mi = 0; mi < 2; mi++)
#pragma unroll
                    for (int ni = 0; ni < 8; ni++) {
                        asm volatile(
                            "mma.sync.aligned.m16n8k8.row.col.f32.tf32.tf32.f32 "
                            "{%0,%1,%2,%3}, {%4,%5,%6,%7}, {%8,%9}, {%0,%1,%2,%3};"
                            : "+f"(d[mi][ni][0]), "+f"(d[mi][ni][1]),
                              "+f"(d[mi][ni][2]), "+f"(d[mi][ni][3])
                            : "r"(a[mi][0]), "r"(a[mi][1]), "r"(a[mi][2]), "r"(a[mi][3]),
                              "r"(b[ni][0]), "r"(b[ni][1]));
                    }
            }
        }
    }

    // epilogue
#pragma unroll
    for (int mi = 0; mi < 2; mi++) {
#pragma unroll
        for (int half = 0; half < 2; half++) {
            int r = rowBase + wm * 32 + mi * 16 + lr + half * 8;
            if (r < ROWS) {
#pragma unroll
                for (int ni = 0; ni < 8; ni++) {
                    int c = wn * 64 + ni * 8 + lc * 2;
                    float p0 = d[mi][ni][half * 2 + 0] + bias[c];
                    float p1 = d[mi][ni][half * 2 + 1] + bias[c + 1];
                    size_t g = (size_t)r * 128 + c;
                    float v0, v1;
                    if (MODE == 0) {
                        v0 = p0; v1 = p1;
                    } else if (MODE == 1) {
                        v0 = 1.f / (1.f + __expf(-p0));
                        v1 = 1.f / (1.f + __expf(-p1));
                    } else if (MODE == 2) {
                        v0 = (1.f / (1.f + __expf(-p0))) * aux[g];
                        v1 = (1.f / (1.f + __expf(-p1))) * aux[g + 1];
                    } else {
                        float z0 = zbuf[g], z1 = zbuf[g + 1];
                        v0 = z0 * aux[g]     + (1.f - z0) * tanhf(p0);
                        v1 = z1 * aux[g + 1] + (1.f - z1) * tanhf(p1);
                    }
                    *(float2*)&out[g] = make_float2(v0, v1);
                }
            }
        }
    }
}

// projections: blockIdx.y==0 -> xl (Wl,bl -> g_buf[0]); ==1 -> xr (Wr,br -> g_buf[1])
__global__ __launch_bounds__(256) void proj_dual_kernel(
    const float* __restrict__ X,
    const float* __restrict__ Wl, const float* __restrict__ bl,
    const float* __restrict__ Wr, const float* __restrict__ br)
{
    const float* W = blockIdx.y ? Wr : Wl;
    const float* b = blockIdx.y ? br : bl;
    float* out = blockIdx.y ? g_buf[1] : g_buf[0];
    gemm_core<1, 0>(X, nullptr, W, b, nullptr, nullptr, out);
}

// gate linear: pre = [F, A2] @ Wlin^T + blin, fused epilogue by MODE.
// A1 = g_buf[2] (F). A2ID>=0 -> g_buf[A2ID], else external a2ext. OUTID likewise.
template<int MODE, int A2ID, int OUTID>
__global__ __launch_bounds__(256) void lin_kernel(
    const float* __restrict__ a2ext, const float* __restrict__ H,
    const float* __restrict__ W, const float* __restrict__ bias,
    float* __restrict__ outext)
{
    const float* A2 = (A2ID >= 0) ? g_buf[A2ID] : a2ext;
    float* out      = (OUTID >= 0) ? g_buf[OUTID] : outext;
    gemm_core<2, MODE>(g_buf[2], A2, W, bias, H, g_buf[3], out);
}

// ------------------------- fused GATv2 edge phase -------------------------
#define CHUNK 64
__global__ __launch_bounds__(128) void gat_agg_kernel(
    const float* __restrict__ att, const float* __restrict__ bias)
{
    const int d = blockIdx.x;
    const int b = blockIdx.y;
    const int tid = threadIdx.x;
    const int lane = tid & 31;
    const int wid = tid >> 5;

    const float* __restrict__ xl = g_buf[0];
    const float* __restrict__ xr = g_buf[1];
    float* __restrict__ Fout = g_buf[2];

    __shared__ float sh_xl[CHUNK][FD];
    __shared__ float sh_w[CHUNK];
    __shared__ int   sh_s[CHUNK];
    __shared__ float sh_xr[FD];
    __shared__ float sh_at[FD];
    __shared__ float red[4];

    const int start = g_rowptr[d];
    const int end   = g_rowptr[d + 1];
    const size_t nb = ((size_t)b * NN + d) * FD;

    sh_xr[tid] = xr[nb + tid];
    sh_at[tid] = att[tid];

    float m_run = -1e30f, denom = 0.f, acc = 0.f;
    __syncthreads();

    for (int cs = start; cs < end; cs += CHUNK) {
        int cn = min(CHUNK, end - cs);
        for (int i = tid; i < cn; i += 128) sh_s[i] = g_csrc[cs + i];
        __syncthreads();
#pragma unroll 4
        for (int i = 0; i < cn; i++)
            sh_xl[i][tid] = xl[((size_t)b * NN + sh_s[i]) * FD + tid];
        __syncthreads();
        for (int i = wid; i < cn; i += 4) {
            float p = 0.f;
#pragma unroll
            for (int q = 0; q < 4; q++) {
                int f = lane + 32 * q;
                float v = sh_xl[i][f] + sh_xr[f];
                v = (v > 0.f) ? v : 0.2f * v;
                p += v * sh_at[f];
            }
#pragma unroll
            for (int o = 16; o > 0; o >>= 1) p += __shfl_xor_sync(0xffffffffu, p, o);
            if (lane == 0) sh_w[i] = p;
        }
        __syncthreads();
        float cm = -1e30f;
        for (int i = tid; i < cn; i += 128) cm = fmaxf(cm, sh_w[i]);
#pragma unroll
        for (int o = 16; o > 0; o >>= 1) cm = fmaxf(cm, __shfl_xor_sync(0xffffffffu, cm, o));
        if (lane == 0) red[wid] = cm;
        __syncthreads();
        float bm = fmaxf(fmaxf(red[0], red[1]), fmaxf(red[2], red[3]));
        float m_new = fmaxf(m_run, bm);
        float rescale = __expf(m_run - m_new);
        denom *= rescale;
        acc   *= rescale;
        __syncthreads();
        float csum = 0.f;
        for (int i = tid; i < cn; i += 128) {
            float w = __expf(sh_w[i] - m_new);
            sh_w[i] = w;
            csum += w;
        }
#pragma unroll
        for (int o = 16; o > 0; o >>= 1) csum += __shfl_xor_sync(0xffffffffu, csum, o);
        if (lane == 0) red[wid] = csum;
        __syncthreads();
        denom += red[0] + red[1] + red[2] + red[3];
#pragma unroll 4
        for (int i = 0; i < cn; i++) acc += sh_w[i] * sh_xl[i][tid];
        m_run = m_new;
        __syncthreads();
    }

    float r = acc / denom + bias[tid];
    Fout[nb + tid] = fmaxf(r, 0.f);
}

// ------------------------- launch -------------------------
extern "C" void kernel_launch(void* const* d_in, const int* in_sizes, int n_in,
                              void* d_out, int out_size)
{
    (void)in_sizes; (void)n_in; (void)out_size;
    const float* X  = (const float*)d_in[0];
    const int*   EI = (const int*)d_in[1];   // int32 (JAX x64 disabled)
    const float* H  = (const float*)d_in[2];

    // per-gate params: Wl, bl, Wr, br, att, bias, Wlin, blin  (z@3, r@11, h@19)
    const float* p[24];
    for (int i = 0; i < 24; i++) p[i] = (const float*)d_in[3 + i];
    const float **gz = p, **gr = p + 8, **gh = p + 16;

    // CSR build (once; shared by all gates)
    init_deg_kernel<<<(NN + 255) / 256, 256>>>();
    count_deg_kernel<<<(MM + 255) / 256, 256>>>(EI);
    scan_kernel<<<1, 1024>>>();
    scatter_csr_kernel<<<(MM + 255) / 256, 256>>>(EI);

    const int GB = (ROWS + 127) / 128;   // 313
    dim3 projGrid(GB, 2);
    dim3 aggGrid(NN, BB);

    // ---- gate z ----
    proj_dual_kernel<<<projGrid, 256>>>(X, gz[0], gz[1], gz[2], gz[3]);
    gat_agg_kernel<<<aggGrid, 128>>>(gz[4], gz[5]);
    lin_kernel<1, -1, 3><<<GB, 256>>>(H, H, gz[6], gz[7], nullptr);        // Z

    // ---- gate r ----
    proj_dual_kernel<<<projGrid, 256>>>(X, gr[0], gr[1], gr[2], gr[3]);
    gat_agg_kernel<<<aggGrid, 128>>>(gr[4], gr[5]);
    lin_kernel<2, -1, 4><<<GB, 256>>>(H, H, gr[6], gr[7], nullptr);        // HR = sigmoid(.)*H

    // ---- gate h ----
    proj_dual_kernel<<<projGrid, 256>>>(X, gh[0], gh[1], gh[2], gh[3]);
    gat_agg_kernel<<<aggGrid, 128>>>(gh[4], gh[5]);
    lin_kernel<3, 4, -1><<<GB, 256>>>(nullptr, H, gh[6], gh[7], (float*)d_out);
}

// round 5
// speedup vs baseline: 2.3093x; 1.5444x over previous
#include <cuda_runtime.h>
#include <math.h>
#include <stdint.h>

#define NN 10000
#define EE 160000
#define MM (EE + NN)   // 170000 edges incl self loops
#define FD 128
#define BB 4
#define ROWS (BB * NN) // 40000

// ------------------------- scratch (device globals; no allocation) -------------------------
// slots: xl[g]=g (0..2), xr[g]=3+g, F[g]=6+g, Z=9, HR=10
__device__ float g_buf[11][(size_t)ROWS * FD];
__device__ int   g_deg[NN];
__device__ int   g_rowptr[NN + 1];
__device__ int   g_cursor[NN];
__device__ int   g_csrc[MM];

struct GateParams {
    const float* W[6];   // (g,side) -> Wl/Wr
    const float* b[6];
};
struct AggParams {
    const float* att[3];
    const float* bias[3];
};

// ------------------------- CSR build -------------------------
__global__ void init_deg_kernel() {
    int i = blockIdx.x * 256 + threadIdx.x;
    if (i < NN) g_deg[i] = 0;
}

__global__ void count_deg_kernel(const int* __restrict__ ei) {
    int m = blockIdx.x * 256 + threadIdx.x;
    if (m >= MM) return;
    int d = (m < EE) ? ei[EE + m] : (m - EE);
    if ((unsigned)d < NN) atomicAdd(&g_deg[d], 1);
}

__global__ void scan_kernel() {
    __shared__ int part[1024];
    int tid = threadIdx.x;
    const int CH = 10;
    int base = tid * CH;
    int loc[CH];
    int s = 0;
#pragma unroll
    for (int i = 0; i < CH; i++) {
        int v = (base + i < NN) ? g_deg[base + i] : 0;
        loc[i] = s; s += v;
    }
    part[tid] = s;
    __syncthreads();
    for (int off = 1; off < 1024; off <<= 1) {
        int add = (tid >= off) ? part[tid - off] : 0;
        __syncthreads();
        part[tid] += add;
        __syncthreads();
    }
    int pre = (tid > 0) ? part[tid - 1] : 0;
#pragma unroll
    for (int i = 0; i < CH; i++) {
        if (base + i < NN) {
            int r = pre + loc[i];
            g_rowptr[base + i] = r;
            g_cursor[base + i] = r;
        }
    }
    if (tid == 1023) g_rowptr[NN] = part[1023];
}

__global__ void scatter_csr_kernel(const int* __restrict__ ei) {
    int m = blockIdx.x * 256 + threadIdx.x;
    if (m >= MM) return;
    int s, d;
    if (m < EE) { s = ei[m]; d = ei[EE + m]; }
    else        { s = d = m - EE; }
    if ((unsigned)d >= NN || (unsigned)s >= NN) return;
    int pos = atomicAdd(&g_cursor[d], 1);
    if (pos < MM) g_csrc[pos] = s;
}

// ------------------------- tf32 tensor-core GEMM core -------------------------
__device__ __forceinline__ float to_tf32(float x) {
    uint32_t u;
    asm("cvt.rna.tf32.f32 %0, %1;" : "=r"(u) : "f"(x));
    return __uint_as_float(u);
}

// MODE 0: pre; 1: sigmoid; 2: sigmoid*aux; 3: zbuf*aux + (1-zbuf)*tanh(pre)
template<int NPH, int MODE>
__device__ __forceinline__ void gemm_core(
    const float* __restrict__ A1, const float* __restrict__ A2,
    const float* __restrict__ W,  const float* __restrict__ bias,
    const float* __restrict__ aux, const float* __restrict__ zbuf,
    float* __restrict__ out)
{
    __shared__ float As[128 * 36];
    __shared__ float Bs[32 * 136];

    const int tid  = threadIdx.x;
    const int lane = tid & 31;
    const int w    = tid >> 5;
    const int wm   = w & 3;
    const int wn   = w >> 2;
    const int lr   = lane >> 2;
    const int lc   = lane & 3;
    const int rowBase = blockIdx.x * 128;
    const int KW = NPH * 128;

    float d[2][8][4];
#pragma unroll
    for (int mi = 0; mi < 2; mi++)
#pragma unroll
        for (int ni = 0; ni < 8; ni++)
#pragma unroll
            for (int q = 0; q < 4; q++) d[mi][ni][q] = 0.f;

#pragma unroll
    for (int ph = 0; ph < NPH; ph++) {
        const float* A = (ph == 0) ? A1 : A2;
#pragma unroll
        for (int kc = 0; kc < 4; kc++) {
            __syncthreads();
#pragma unroll
            for (int i = 0; i < 4; i++) {
                int idx = tid + i * 256;
                int row = idx >> 3, kg = idx & 7;
                int gr = rowBase + row;
                if (gr >= ROWS) gr = ROWS - 1;
                float4 v = *(const float4*)(A + (size_t)gr * 128 + kc * 32 + kg * 4);
                *(float4*)&As[row * 36 + kg * 4] =
                    make_float4(to_tf32(v.x), to_tf32(v.y), to_tf32(v.z), to_tf32(v.w));
            }
#pragma unroll
            for (int i = 0; i < 4; i++) {
                int idx = tid + i * 256;
                int n = idx & 127, kg = idx >> 7;
                float4 v = *(const float4*)(W + (size_t)n * KW + ph * 128 + kc * 32 + kg * 4);
                Bs[(kg * 4 + 0) * 136 + n] = to_tf32(v.x);
                Bs[(kg * 4 + 1) * 136 + n] = to_tf32(v.y);
                Bs[(kg * 4 + 2) * 136 + n] = to_tf32(v.z);
                Bs[(kg * 4 + 3) * 136 + n] = to_tf32(v.w);
            }
            __syncthreads();

#pragma unroll
            for (int ks = 0; ks < 4; ks++) {
                uint32_t a[2][4], b[8][2];
#pragma unroll
                for (int mi = 0; mi < 2; mi++) {
                    int r = wm * 32 + mi * 16 + lr;
                    a[mi][0] = __float_as_uint(As[(r    ) * 36 + ks * 8 + lc    ]);
                    a[mi][1] = __float_as_uint(As[(r + 8) * 36 + ks * 8 + lc    ]);
                    a[mi][2] = __float_as_uint(As[(r    ) * 36 + ks * 8 + lc + 4]);
                    a[mi][3] = __float_as_uint(As[(r + 8) * 36 + ks * 8 + lc + 4]);
                }
#pragma unroll
                for (int ni = 0; ni < 8; ni++) {
                    int n = wn * 64 + ni * 8 + lr;
                    b[ni][0] = __float_as_uint(Bs[(ks * 8 + lc    ) * 136 + n]);
                    b[ni][1] = __float_as_uint(Bs[(ks * 8 + lc + 4) * 136 + n]);
                }
#pragma unroll
                for (int mi = 0; mi < 2; mi++)
#pragma unroll
                    for (int ni = 0; ni < 8; ni++) {
                        asm volatile(
                            "mma.sync.aligned.m16n8k8.row.col.f32.tf32.tf32.f32 "
                            "{%0,%1,%2,%3}, {%4,%5,%6,%7}, {%8,%9}, {%0,%1,%2,%3};"
                            : "+f"(d[mi][ni][0]), "+f"(d[mi][ni][1]),
                              "+f"(d[mi][ni][2]), "+f"(d[mi][ni][3])
                            : "r"(a[mi][0]), "r"(a[mi][1]), "r"(a[mi][2]), "r"(a[mi][3]),
                              "r"(b[ni][0]), "r"(b[ni][1]));
                    }
            }
        }
    }

#pragma unroll
    for (int mi = 0; mi < 2; mi++) {
#pragma unroll
        for (int half = 0; half < 2; half++) {
            int r = rowBase + wm * 32 + mi * 16 + lr + half * 8;
            if (r < ROWS) {
#pragma unroll
                for (int ni = 0; ni < 8; ni++) {
                    int c = wn * 64 + ni * 8 + lc * 2;
                    float p0 = d[mi][ni][half * 2 + 0] + bias[c];
                    float p1 = d[mi][ni][half * 2 + 1] + bias[c + 1];
                    size_t g = (size_t)r * 128 + c;
                    float v0, v1;
                    if (MODE == 0) {
                        v0 = p0; v1 = p1;
                    } else if (MODE == 1) {
                        v0 = 1.f / (1.f + __expf(-p0));
                        v1 = 1.f / (1.f + __expf(-p1));
                    } else if (MODE == 2) {
                        v0 = (1.f / (1.f + __expf(-p0))) * aux[g];
                        v1 = (1.f / (1.f + __expf(-p1))) * aux[g + 1];
                    } else {
                        float z0 = zbuf[g], z1 = zbuf[g + 1];
                        v0 = z0 * aux[g]     + (1.f - z0) * tanhf(p0);
                        v1 = z1 * aux[g + 1] + (1.f - z1) * tanhf(p1);
                    }
                    *(float2*)&out[g] = make_float2(v0, v1);
                }
            }
        }
    }
}

// all 6 projections (3 gates x {l,r}) in one launch: blockIdx.y = g*2+side
__global__ __launch_bounds__(256) void proj_all_kernel(
    const float* __restrict__ X, GateParams gp)
{
    int y = blockIdx.y;
    int g = y >> 1, side = y & 1;
    float* out = g_buf[side * 3 + g];
    gemm_core<1, 0>(X, nullptr, gp.W[y], gp.b[y], nullptr, nullptr, out);
}

// lin z (MODE1 -> Z=g_buf[9]) and lin r (MODE2 -> HR=g_buf[10]) fused: blockIdx.y picks
__global__ __launch_bounds__(256) void lin_zr_kernel(
    const float* __restrict__ H,
    const float* __restrict__ Wz, const float* __restrict__ bz,
    const float* __restrict__ Wr, const float* __restrict__ br)
{
    if (blockIdx.y == 0)
        gemm_core<2, 1>(g_buf[6], H, Wz, bz, H, nullptr, g_buf[9]);
    else
        gemm_core<2, 2>(g_buf[7], H, Wr, br, H, nullptr, g_buf[10]);
}

__global__ __launch_bounds__(256) void lin_h_kernel(
    const float* __restrict__ H,
    const float* __restrict__ W, const float* __restrict__ bias,
    float* __restrict__ out)
{
    gemm_core<2, 3>(g_buf[8], g_buf[10], W, bias, H, g_buf[9], out);
}

// ------------------------- warp-per-destination GATv2 aggregation -------------------------
// One warp handles (gate, batch, dst). Lanes = features (4/lane). No smem, no block sync.
// Chunked exact softmax: per chunk of <=64 edges compute e (ILP), chunk max/exp/sum via
// shuffles, then weighted accumulation; exact online rescale across chunks.
#define ACHUNK 64
__global__ __launch_bounds__(256) void gat_agg_kernel(AggParams ap)
{
    const int lane = threadIdx.x & 31;
    const int gw = blockIdx.x * 8 + (threadIdx.x >> 5);
    if (gw >= 3 * BB * NN) return;
    const int g = gw / (BB * NN);
    const int rem = gw - g * (BB * NN);
    const int b = rem / NN;
    const int d = rem - b * NN;

    const float* __restrict__ xl = g_buf[g];
    const float* __restrict__ xr = g_buf[3 + g];
    float* __restrict__ Fout = g_buf[6 + g];
    const float* __restrict__ att = ap.att[g];
    const float* __restrict__ bias = ap.bias[g];

    const int start = g_rowptr[d];
    const int end   = g_rowptr[d + 1];
    const size_t nb = ((size_t)b * NN + d) * FD;
    const size_t bbase = (size_t)b * NN;

    float xr_v[4], at_v[4], acc[4];
#pragma unroll
    for (int q = 0; q < 4; q++) {
        xr_v[q] = xr[nb + lane + 32 * q];
        at_v[q] = att[lane + 32 * q];
        acc[q] = 0.f;
    }
    float m_run = -1e30f, denom = 0.f;

    for (int cs = start; cs < end; cs += ACHUNK) {
        const int cn = min(ACHUNK, end - cs);
        // preload src indices: lane l holds edges cs + j*32 + l
        int sidx[2];
#pragma unroll
        for (int j = 0; j < 2; j++) {
            int i = j * 32 + lane;
            sidx[j] = (i < cn) ? g_csrc[cs + i] : 0;
        }
        // phase A: e for each edge (warp-cooperative dot, independent across edges)
        float e_loc[2] = {-1e30f, -1e30f};
#pragma unroll
        for (int j = 0; j < 2; j++) {
            for (int l = 0; l < 32; l++) {
                int i = j * 32 + l;
                if (i >= cn) break;
                int s = __shfl_sync(0xffffffffu, sidx[j], l);
                const float* row = xl + (bbase + s) * FD;
                float p = 0.f;
#pragma unroll
                for (int q = 0; q < 4; q++) {
                    float v = row[lane + 32 * q] + xr_v[q];
                    v = (v > 0.f) ? v : 0.2f * v;
                    p += v * at_v[q];
                }
#pragma unroll
                for (int o = 16; o > 0; o >>= 1)
                    p += __shfl_xor_sync(0xffffffffu, p, o);
                if (lane == l) e_loc[j] = p;
            }
        }
        // phase B: chunk max, rescale, exp, chunk denom
        float cm = fmaxf(e_loc[0], e_loc[1]);
#pragma unroll
        for (int o = 16; o > 0; o >>= 1)
            cm = fmaxf(cm, __shfl_xor_sync(0xffffffffu, cm, o));
        float m_new = fmaxf(m_run, cm);
        float rescale = __expf(m_run - m_new);
        denom *= rescale;
#pragma unroll
        for (int q = 0; q < 4; q++) acc[q] *= rescale;
        float p_loc[2];
        float csum = 0.f;
#pragma unroll
        for (int j = 0; j < 2; j++) {
            int i = j * 32 + lane;
            p_loc[j] = (i < cn) ? __expf(e_loc[j] - m_new) : 0.f;
            csum += p_loc[j];
        }
#pragma unroll
        for (int o = 16; o > 0; o >>= 1)
            csum += __shfl_xor_sync(0xffffffffu, csum, o);
        denom += csum;
        // phase C: weighted accumulation (rows re-read: L1/L2 hits)
#pragma unroll
        for (int j = 0; j < 2; j++) {
            for (int l = 0; l < 32; l++) {
                int i = j * 32 + l;
                if (i >= cn) break;
                int s = __shfl_sync(0xffffffffu, sidx[j], l);
                float wgt = __shfl_sync(0xffffffffu, p_loc[j], l);
                const float* row = xl + (bbase + s) * FD;
#pragma unroll
                for (int q = 0; q < 4; q++)
                    acc[q] += wgt * row[lane + 32 * q];
            }
        }
        m_run = m_new;
    }

    float inv = 1.f / denom;
#pragma unroll
    for (int q = 0; q < 4; q++) {
        float r = acc[q] * inv + bias[lane + 32 * q];
        Fout[nb + lane + 32 * q] = fmaxf(r, 0.f);
    }
}

// ------------------------- launch -------------------------
extern "C" void kernel_launch(void* const* d_in, const int* in_sizes, int n_in,
                              void* d_out, int out_size)
{
    (void)in_sizes; (void)n_in; (void)out_size;
    const float* X  = (const float*)d_in[0];
    const int*   EI = (const int*)d_in[1];   // int32 (JAX x64 disabled)
    const float* H  = (const float*)d_in[2];

    // per-gate params: Wl, bl, Wr, br, att, bias, Wlin, blin  (z@3, r@11, h@19)
    const float* p[24];
    for (int i = 0; i < 24; i++) p[i] = (const float*)d_in[3 + i];
    const float **gz = p, **gr = p + 8, **gh = p + 16;

    // CSR build (once; shared by all gates)
    init_deg_kernel<<<(NN + 255) / 256, 256>>>();
    count_deg_kernel<<<(MM + 255) / 256, 256>>>(EI);
    scan_kernel<<<1, 1024>>>();
    scatter_csr_kernel<<<(MM + 255) / 256, 256>>>(EI);

    const int GB = (ROWS + 127) / 128;   // 313

    GateParams gp;
    for (int g = 0; g < 3; g++) {
        gp.W[g * 2 + 0] = p[g * 8 + 0]; gp.b[g * 2 + 0] = p[g * 8 + 1];
        gp.W[g * 2 + 1] = p[g * 8 + 2]; gp.b[g * 2 + 1] = p[g * 8 + 3];
    }
    AggParams ap;
    ap.att[0] = gz[4]; ap.bias[0] = gz[5];
    ap.att[1] = gr[4]; ap.bias[1] = gr[5];
    ap.att[2] = gh[4]; ap.bias[2] = gh[5];

    // all 6 projections
    dim3 projGrid(GB, 6);
    proj_all_kernel<<<projGrid, 256>>>(X, gp);

    // all 3 gates' aggregation in one launch (warp per (g,b,d))
    int nwarps = 3 * BB * NN;
    gat_agg_kernel<<<(nwarps + 7) / 8, 256>>>(ap);

    // lin z + lin r fused, then lin h
    dim3 linGrid(GB, 2);
    lin_zr_kernel<<<linGrid, 256>>>(H, gz[6], gz[7], gr[6], gr[7]);
    lin_h_kernel<<<GB, 256>>>(H, gh[6], gh[7], (float*)d_out);
}

// round 8
// speedup vs baseline: 3.0143x; 1.3053x over previous
#include <cuda_runtime.h>
#include <math.h>
#include <stdint.h>

#define NN 10000
#define EE 160000
#define MM (EE + NN)   // 170000 edges incl self loops
#define FD 128
#define BB 4
#define ROWS (BB * NN) // 40000

// ------------------------- scratch (device globals; no allocation) -------------------------
// slots: xl[g]=g (0..2), xr[g]=3+g, F[g]=6+g, Z=9, HR=10
__device__ float g_buf[11][(size_t)ROWS * FD];
__device__ int   g_deg[NN];
__device__ int   g_rowptr[NN + 1];
__device__ int   g_cursor[NN];
__device__ int   g_csrc[MM];

struct GateParams {
    const float* W[6];   // (g,side) -> Wl/Wr
    const float* b[6];
};
struct AggParams {
    const float* att[3];
    const float* bias[3];
};

// ------------------------- CSR build -------------------------
__global__ void init_deg_kernel() {
    int i = blockIdx.x * 256 + threadIdx.x;
    if (i < NN) g_deg[i] = 0;
}

__global__ void count_deg_kernel(const int* __restrict__ ei) {
    int m = blockIdx.x * 256 + threadIdx.x;
    if (m >= MM) return;
    int d = (m < EE) ? ei[EE + m] : (m - EE);
    if ((unsigned)d < NN) atomicAdd(&g_deg[d], 1);
}

__global__ void scan_kernel() {
    __shared__ int part[1024];
    int tid = threadIdx.x;
    const int CH = 10;
    int base = tid * CH;
    int loc[CH];
    int s = 0;
#pragma unroll
    for (int i = 0; i < CH; i++) {
        int v = (base + i < NN) ? g_deg[base + i] : 0;
        loc[i] = s; s += v;
    }
    part[tid] = s;
    __syncthreads();
    for (int off = 1; off < 1024; off <<= 1) {
        int add = (tid >= off) ? part[tid - off] : 0;
        __syncthreads();
        part[tid] += add;
        __syncthreads();
    }
    int pre = (tid > 0) ? part[tid - 1] : 0;
#pragma unroll
    for (int i = 0; i < CH; i++) {
        if (base + i < NN) {
            int r = pre + loc[i];
            g_rowptr[base + i] = r;
            g_cursor[base + i] = r;
        }
    }
    if (tid == 1023) g_rowptr[NN] = part[1023];
}

__global__ void scatter_csr_kernel(const int* __restrict__ ei) {
    int m = blockIdx.x * 256 + threadIdx.x;
    if (m >= MM) return;
    int s, d;
    if (m < EE) { s = ei[m]; d = ei[EE + m]; }
    else        { s = d = m - EE; }
    if ((unsigned)d >= NN || (unsigned)s >= NN) return;
    int pos = atomicAdd(&g_cursor[d], 1);
    if (pos < MM) g_csrc[pos] = s;
}

// ------------------------- tf32 tensor-core GEMM (cp.async double-buffered) -------------------------
// C[r,o] = sum_f A(f) * W[o,f] (+bias, fused epilogue).
// Block tile 128x128, 256 threads (8 warps: 4m x 2n), warp tile m32 x n64.
// Tiles staged untransposed: As[row][k] pad 36, Bs[n][k] pad 36 (pure 16B cp.async).
// HW truncation of fp32 -> tf32 inside HMMA (no explicit cvt).
#define TILE_F (128 * 36)          // floats per tile
#define GEMM_SMEM_BYTES (2 * 2 * TILE_F * 4)   // 2 buffers x (A+B)

__device__ __forceinline__ void cp_async16(float* s, const float* g) {
    uint32_t sa = (uint32_t)__cvta_generic_to_shared(s);
    asm volatile("cp.async.cg.shared.global [%0], [%1], 16;" :: "r"(sa), "l"(g));
}
__device__ __forceinline__ void cp_commit() {
    asm volatile("cp.async.commit_group;");
}

// MODE 0: pre; 1: sigmoid; 2: sigmoid*aux; 3: zbuf*aux + (1-zbuf)*tanh(pre)
template<int NPH, int MODE>
__device__ __forceinline__ void gemm_core(
    const float* __restrict__ A1, const float* __restrict__ A2,
    const float* __restrict__ W,  const float* __restrict__ bias,
    const float* __restrict__ aux, const float* __restrict__ zbuf,
    float* __restrict__ out)
{
    extern __shared__ float dynsm[];

    const int tid  = threadIdx.x;
    const int lane = tid & 31;
    const int w    = tid >> 5;
    const int wm   = w & 3;
    const int wn   = w >> 2;
    const int lr   = lane >> 2;
    const int lc   = lane & 3;
    const int rowBase = blockIdx.x * 128;
    const int KW = NPH * 128;
    const int NC = NPH * 4;          // number of 32-k chunks

    float d[2][8][4];
#pragma unroll
    for (int mi = 0; mi < 2; mi++)
#pragma unroll
        for (int ni = 0; ni < 8; ni++)
#pragma unroll
            for (int q = 0; q < 4; q++) d[mi][ni][q] = 0.f;

    // issue loads for chunk c into buffer buf
    auto issue = [&](int c, int buf) {
        const float* A = (c >= 4) ? A2 : A1;
        const int kc = c & 3;
        float* As = dynsm + buf * 2 * TILE_F;
        float* Bs = As + TILE_F;
#pragma unroll
        for (int i = 0; i < 4; i++) {
            int idx = tid + i * 256;
            int row = idx >> 3, kg = idx & 7;
            int gr = rowBase + row;
            if (gr >= ROWS) gr = ROWS - 1;
            cp_async16(&As[row * 36 + kg * 4], A + (size_t)gr * 128 + kc * 32 + kg * 4);
        }
#pragma unroll
        for (int i = 0; i < 4; i++) {
            int idx = tid + i * 256;
            int n = idx >> 3, kg = idx & 7;
            cp_async16(&Bs[n * 36 + kg * 4], W + (size_t)n * KW + (c >> 2) * 128 + kc * 32 + kg * 4);
        }
        cp_commit();
    };

    issue(0, 0);
    for (int c = 0; c < NC; c++) {
        if (c + 1 < NC) {
            issue(c + 1, (c + 1) & 1);
            asm volatile("cp.async.wait_group 1;");
        } else {
            asm volatile("cp.async.wait_group 0;");
        }
        __syncthreads();

        const float* As = dynsm + (c & 1) * 2 * TILE_F;
        const float* Bs = As + TILE_F;
#pragma unroll
        for (int ks = 0; ks < 4; ks++) {
            uint32_t a[2][4], b[8][2];
#pragma unroll
            for (int mi = 0; mi < 2; mi++) {
                int r = wm * 32 + mi * 16 + lr;
                a[mi][0] = __float_as_uint(As[(r    ) * 36 + ks * 8 + lc    ]);
                a[mi][1] = __float_as_uint(As[(r + 8) * 36 + ks * 8 + lc    ]);
                a[mi][2] = __float_as_uint(As[(r    ) * 36 + ks * 8 + lc + 4]);
                a[mi][3] = __float_as_uint(As[(r + 8) * 36 + ks * 8 + lc + 4]);
            }
#pragma unroll
            for (int ni = 0; ni < 8; ni++) {
                int n = wn * 64 + ni * 8 + lr;
                b[ni][0] = __float_as_uint(Bs[n * 36 + ks * 8 + lc    ]);
                b[ni][1] = __float_as_uint(Bs[n * 36 + ks * 8 + lc + 4]);
            }
#pragma unroll
            for (int mi = 0; mi < 2; mi++)
#pragma unroll
                for (int ni = 0; ni < 8; ni++) {
                    asm volatile(
                        "mma.sync.aligned.m16n8k8.row.col.f32.tf32.tf32.f32 "
                        "{%0,%1,%2,%3}, {%4,%5,%6,%7}, {%8,%9}, {%0,%1,%2,%3};"
                        : "+f"(d[mi][ni][0]), "+f"(d[mi][ni][1]),
                          "+f"(d[mi][ni][2]), "+f"(d[mi][ni][3])
                        : "r"(a[mi][0]), "r"(a[mi][1]), "r"(a[mi][2]), "r"(a[mi][3]),
                          "r"(b[ni][0]), "r"(b[ni][1]));
                }
        }
        __syncthreads();   // buffer (c&1) free for chunk c+2's issue
    }

    // epilogue
#pragma unroll
    for (int mi = 0; mi < 2; mi++) {
#pragma unroll
        for (int half = 0; half < 2; half++) {
            int r = rowBase + wm * 32 + mi * 16 + lr + half * 8;
            if (r < ROWS) {
#pragma unroll
                for (int ni = 0; ni < 8; ni++) {
                    int c = wn * 64 + ni * 8 + lc * 2;
                    float p0 = d[mi][ni][half * 2 + 0] + bias[c];
                    float p1 = d[mi][ni][half * 2 + 1] + bias[c + 1];
                    size_t g = (size_t)r * 128 + c;
                    float v0, v1;
                    if (MODE == 0) {
                        v0 = p0; v1 = p1;
                    } else if (MODE == 1) {
                        v0 = 1.f / (1.f + __expf(-p0));
                        v1 = 1.f / (1.f + __expf(-p1));
                    } else if (MODE == 2) {
                        v0 = (1.f / (1.f + __expf(-p0))) * aux[g];
                        v1 = (1.f / (1.f + __expf(-p1))) * aux[g + 1];
                    } else {
                        float z0 = zbuf[g], z1 = zbuf[g + 1];
                        v0 = z0 * aux[g]     + (1.f - z0) * tanhf(p0);
                        v1 = z1 * aux[g + 1] + (1.f - z1) * tanhf(p1);
                    }
                    *(float2*)&out[g] = make_float2(v0, v1);
                }
            }
        }
    }
}

// all 6 projections (3 gates x {l,r}) in one launch: blockIdx.y = g*2+side
__global__ __launch_bounds__(256) void proj_all_kernel(
    const float* __restrict__ X, GateParams gp)
{
    int y = blockIdx.y;
    int g = y >> 1, side = y & 1;
    float* out = g_buf[side * 3 + g];
    gemm_core<1, 0>(X, nullptr, gp.W[y], gp.b[y], nullptr, nullptr, out);
}

// lin z (MODE1 -> Z=g_buf[9]) and lin r (MODE2 -> HR=g_buf[10]) fused
__global__ __launch_bounds__(256) void lin_zr_kernel(
    const float* __restrict__ H,
    const float* __restrict__ Wz, const float* __restrict__ bz,
    const float* __restrict__ Wr, const float* __restrict__ br)
{
    if (blockIdx.y == 0)
        gemm_core<2, 1>(g_buf[6], H, Wz, bz, H, nullptr, g_buf[9]);
    else
        gemm_core<2, 2>(g_buf[7], H, Wr, br, H, nullptr, g_buf[10]);
}

__global__ __launch_bounds__(256) void lin_h_kernel(
    const float* __restrict__ H,
    const float* __restrict__ W, const float* __restrict__ bias,
    float* __restrict__ out)
{
    gemm_core<2, 3>(g_buf[8], g_buf[10], W, bias, H, g_buf[9], out);
}

// ------------------------- warp-per-destination GATv2 aggregation -------------------------
#define ACHUNK 64
__global__ __launch_bounds__(256) void gat_agg_kernel(AggParams ap)
{
    const int lane = threadIdx.x & 31;
    const int gw = blockIdx.x * 8 + (threadIdx.x >> 5);
    if (gw >= 3 * BB * NN) return;
    const int g = gw / (BB * NN);
    const int rem = gw - g * (BB * NN);
    const int b = rem / NN;
    const int d = rem - b * NN;

    const float* __restrict__ xl = g_buf[g];
    const float* __restrict__ xr = g_buf[3 + g];
    float* __restrict__ Fout = g_buf[6 + g];
    const float* __restrict__ att = ap.att[g];
    const float* __restrict__ bias = ap.bias[g];

    const int start = g_rowptr[d];
    const int end   = g_rowptr[d + 1];
    const size_t nb = ((size_t)b * NN + d) * FD;
    const size_t bbase = (size_t)b * NN;

    float xr_v[4], at_v[4], acc[4];
#pragma unroll
    for (int q = 0; q < 4; q++) {
        xr_v[q] = xr[nb + lane + 32 * q];
        at_v[q] = att[lane + 32 * q];
        acc[q] = 0.f;
    }
    float m_run = -1e30f, denom = 0.f;

    for (int cs = start; cs < end; cs += ACHUNK) {
        const int cn = min(ACHUNK, end - cs);
        int sidx[2];
#pragma unroll
        for (int j = 0; j < 2; j++) {
            int i = j * 32 + lane;
            sidx[j] = (i < cn) ? g_csrc[cs + i] : 0;
        }
        float e_loc[2] = {-1e30f, -1e30f};
#pragma unroll
        for (int j = 0; j < 2; j++) {
            for (int l = 0; l < 32; l++) {
                int i = j * 32 + l;
                if (i >= cn) break;
                int s = __shfl_sync(0xffffffffu, sidx[j], l);
                const float* row = xl + (bbase + s) * FD;
                float p = 0.f;
#pragma unroll
                for (int q = 0; q < 4; q++) {
                    float v = row[lane + 32 * q] + xr_v[q];
                    v = (v > 0.f) ? v : 0.2f * v;
                    p += v * at_v[q];
                }
#pragma unroll
                for (int o = 16; o > 0; o >>= 1)
                    p += __shfl_xor_sync(0xffffffffu, p, o);
                if (lane == l) e_loc[j] = p;
            }
        }
        float cm = fmaxf(e_loc[0], e_loc[1]);
#pragma unroll
        for (int o = 16; o > 0; o >>= 1)
            cm = fmaxf(cm, __shfl_xor_sync(0xffffffffu, cm, o));
        float m_new = fmaxf(m_run, cm);
        float rescale = __expf(m_run - m_new);
        denom *= rescale;
#pragma unroll
        for (int q = 0; q < 4; q++) acc[q] *= rescale;
        float p_loc[2];
        float csum = 0.f;
#pragma unroll
        for (int j = 0; j < 2; j++) {
            int i = j * 32 + lane;
            p_loc[j] = (i < cn) ? __expf(e_loc[j] - m_new) : 0.f;
            csum += p_loc[j];
        }
#pragma unroll
        for (int o = 16; o > 0; o >>= 1)
            csum += __shfl_xor_sync(0xffffffffu, csum, o);
        denom += csum;
#pragma unroll
        for (int j = 0; j < 2; j++) {
            for (int l = 0; l < 32; l++) {
                int i = j * 32 + l;
                if (i >= cn) break;
                int s = __shfl_sync(0xffffffffu, sidx[j], l);
                float wgt = __shfl_sync(0xffffffffu, p_loc[j], l);
                const float* row = xl + (bbase + s) * FD;
#pragma unroll
                for (int q = 0; q < 4; q++)
                    acc[q] += wgt * row[lane + 32 * q];
            }
        }
        m_run = m_new;
    }

    float inv = 1.f / denom;
#pragma unroll
    for (int q = 0; q < 4; q++) {
        float r = acc[q] * inv + bias[lane + 32 * q];
        Fout[nb + lane + 32 * q] = fmaxf(r, 0.f);
    }
}

// ------------------------- launch -------------------------
extern "C" void kernel_launch(void* const* d_in, const int* in_sizes, int n_in,
                              void* d_out, int out_size)
{
    (void)in_sizes; (void)n_in; (void)out_size;
    const float* X  = (const float*)d_in[0];
    const int*   EI = (const int*)d_in[1];   // int32 (JAX x64 disabled)
    const float* H  = (const float*)d_in[2];

    // per-gate params: Wl, bl, Wr, br, att, bias, Wlin, blin  (z@3, r@11, h@19)
    const float* p[24];
    for (int i = 0; i < 24; i++) p[i] = (const float*)d_in[3 + i];
    const float **gz = p, **gr = p + 8, **gh = p + 16;

    // idempotent, host-side, executes immediately (not captured) — no static guard
    cudaFuncSetAttribute(proj_all_kernel, cudaFuncAttributeMaxDynamicSharedMemorySize, GEMM_SMEM_BYTES);
    cudaFuncSetAttribute(lin_zr_kernel,   cudaFuncAttributeMaxDynamicSharedMemorySize, GEMM_SMEM_BYTES);
    cudaFuncSetAttribute(lin_h_kernel,    cudaFuncAttributeMaxDynamicSharedMemorySize, GEMM_SMEM_BYTES);

    // CSR build (once; shared by all gates)
    init_deg_kernel<<<(NN + 255) / 256, 256>>>();
    count_deg_kernel<<<(MM + 255) / 256, 256>>>(EI);
    scan_kernel<<<1, 1024>>>();
    scatter_csr_kernel<<<(MM + 255) / 256, 256>>>(EI);

    const int GB = (ROWS + 127) / 128;   // 313

    GateParams gp;
    for (int g = 0; g < 3; g++) {
        gp.W[g * 2 + 0] = p[g * 8 + 0]; gp.b[g * 2 + 0] = p[g * 8 + 1];
        gp.W[g * 2 + 1] = p[g * 8 + 2]; gp.b[g * 2 + 1] = p[g * 8 + 3];
    }
    AggParams ap;
    ap.att[0] = gz[4]; ap.bias[0] = gz[5];
    ap.att[1] = gr[4]; ap.bias[1] = gr[5];
    ap.att[2] = gh[4]; ap.bias[2] = gh[5];

    dim3 projGrid(GB, 6);
    proj_all_kernel<<<projGrid, 256, GEMM_SMEM_BYTES>>>(X, gp);

    int nwarps = 3 * BB * NN;
    gat_agg_kernel<<<(nwarps + 7) / 8, 256>>>(ap);

    dim3 linGrid(GB, 2);
    lin_zr_kernel<<<linGrid, 256, GEMM_SMEM_BYTES>>>(H, gz[6], gz[7], gr[6], gr[7]);
    lin_h_kernel<<<GB, 256, GEMM_SMEM_BYTES>>>(H, gh[6], gh[7], (float*)d_out);
}

// round 12
// speedup vs baseline: 3.6397x; 1.2075x over previous
#include <cuda_runtime.h>
#include <math.h>
#include <stdint.h>

#define NN 10000
#define EE 160000
#define MM (EE + NN)   // 170000 edges incl self loops
#define FD 128
#define BB 4
#define ROWS (BB * NN) // 40000

// ------------------------- scratch (device globals; no allocation) -------------------------
// slots: xl[g]=g (0..2), xr[g]=3+g, F[g]=6+g, Z=9, HR=10
__device__ float g_buf[11][(size_t)ROWS * FD];
__device__ int   g_deg[NN];
__device__ int   g_rowptr[NN + 1];
__device__ int   g_cursor[NN];
__device__ int   g_csrc[MM];

struct GateParams {
    const float* W[6];   // (g,side) -> Wl/Wr
    const float* b[6];
};
struct AggParams {
    const float* att[3];
    const float* bias[3];
};

// ------------------------- CSR build -------------------------
__global__ void init_deg_kernel() {
    int i = blockIdx.x * 256 + threadIdx.x;
    if (i < NN) g_deg[i] = 0;
}

__global__ void count_deg_kernel(const int* __restrict__ ei) {
    int m = blockIdx.x * 256 + threadIdx.x;
    if (m >= MM) return;
    int d = (m < EE) ? ei[EE + m] : (m - EE);
    if ((unsigned)d < NN) atomicAdd(&g_deg[d], 1);
}

__global__ void scan_kernel() {
    __shared__ int part[1024];
    int tid = threadIdx.x;
    const int CH = 10;
    int base = tid * CH;
    int loc[CH];
    int s = 0;
#pragma unroll
    for (int i = 0; i < CH; i++) {
        int v = (base + i < NN) ? g_deg[base + i] : 0;
        loc[i] = s; s += v;
    }
    part[tid] = s;
    __syncthreads();
    for (int off = 1; off < 1024; off <<= 1) {
        int add = (tid >= off) ? part[tid - off] : 0;
        __syncthreads();
        part[tid] += add;
        __syncthreads();
    }
    int pre = (tid > 0) ? part[tid - 1] : 0;
#pragma unroll
    for (int i = 0; i < CH; i++) {
        if (base + i < NN) {
            int r = pre + loc[i];
            g_rowptr[base + i] = r;
            g_cursor[base + i] = r;
        }
    }
    if (tid == 1023) g_rowptr[NN] = part[1023];
}

__global__ void scatter_csr_kernel(const int* __restrict__ ei) {
    int m = blockIdx.x * 256 + threadIdx.x;
    if (m >= MM) return;
    int s, d;
    if (m < EE) { s = ei[m]; d = ei[EE + m]; }
    else        { s = d = m - EE; }
    if ((unsigned)d >= NN || (unsigned)s >= NN) return;
    int pos = atomicAdd(&g_cursor[d], 1);
    if (pos < MM) g_csrc[pos] = s;
}

// ------------------------- tf32 tensor-core GEMM (cp.async 3-stage ring) -------------------------
// C[r,o] = sum_f A(f) * W[o,f] (+bias, fused epilogue).
// Block tile 128x128, 256 threads (8 warps: 4m x 2n), warp tile m32 x n64.
// Tiles staged untransposed: As[row][k] pad 36, Bs[n][k] pad 36 (pure 16B cp.async).
// HW truncation of fp32 -> tf32 inside HMMA (no explicit cvt).
#define TILE_F (128 * 36)                      // floats per tile (18KB)
#define GEMM_SMEM_BYTES (3 * 2 * TILE_F * 4)   // 3 stages x (A+B) = 108KB

__device__ __forceinline__ void cp_async16(float* s, const float* g) {
    uint32_t sa = (uint32_t)__cvta_generic_to_shared(s);
    asm volatile("cp.async.cg.shared.global [%0], [%1], 16;" :: "r"(sa), "l"(g));
}
__device__ __forceinline__ void cp_commit() {
    asm volatile("cp.async.commit_group;");
}

// MODE 0: pre; 1: sigmoid; 2: sigmoid*aux; 3: zbuf*aux + (1-zbuf)*tanh(pre)
template<int NPH, int MODE>
__device__ __forceinline__ void gemm_core(
    const float* __restrict__ A1, const float* __restrict__ A2,
    const float* __restrict__ W,  const float* __restrict__ bias,
    const float* __restrict__ aux, const float* __restrict__ zbuf,
    float* __restrict__ out)
{
    extern __shared__ float dynsm[];

    const int tid  = threadIdx.x;
    const int lane = tid & 31;
    const int w    = tid >> 5;
    const int wm   = w & 3;
    const int wn   = w >> 2;
    const int lr   = lane >> 2;
    const int lc   = lane & 3;
    const int rowBase = blockIdx.x * 128;
    const int KW = NPH * 128;
    const int NC = NPH * 4;          // number of 32-k chunks

    float d[2][8][4];
#pragma unroll
    for (int mi = 0; mi < 2; mi++)
#pragma unroll
        for (int ni = 0; ni < 8; ni++)
#pragma unroll
            for (int q = 0; q < 4; q++) d[mi][ni][q] = 0.f;

    // issue loads for chunk c into stage buf
    auto issue = [&](int c, int buf) {
        const float* A = (c >= 4) ? A2 : A1;
        const int kc = c & 3;
        float* As = dynsm + buf * 2 * TILE_F;
        float* Bs = As + TILE_F;
#pragma unroll
        for (int i = 0; i < 4; i++) {
            int idx = tid + i * 256;
            int row = idx >> 3, kg = idx & 7;
            int gr = rowBase + row;
            if (gr >= ROWS) gr = ROWS - 1;
            cp_async16(&As[row * 36 + kg * 4], A + (size_t)gr * 128 + kc * 32 + kg * 4);
        }
#pragma unroll
        for (int i = 0; i < 4; i++) {
            int idx = tid + i * 256;
            int n = idx >> 3, kg = idx & 7;
            cp_async16(&Bs[n * 36 + kg * 4], W + (size_t)n * KW + (c >> 2) * 128 + kc * 32 + kg * 4);
        }
        cp_commit();
    };

    issue(0, 0);
    if (NC > 1) issue(1, 1);

    for (int c = 0; c < NC; c++) {
        if (c + 1 < NC) asm volatile("cp.async.wait_group 1;");
        else            asm volatile("cp.async.wait_group 0;");
        __syncthreads();             // chunk c visible to all; stage (c+2)%3 free
        if (c + 2 < NC) issue(c + 2, (c + 2) % 3);

        const float* As = dynsm + (c % 3) * 2 * TILE_F;
        const float* Bs = As + TILE_F;
#pragma unroll
        for (int ks = 0; ks < 4; ks++) {
            uint32_t a[2][4], b[8][2];
#pragma unroll
            for (int mi = 0; mi < 2; mi++) {
                int r = wm * 32 + mi * 16 + lr;
                a[mi][0] = __float_as_uint(As[(r    ) * 36 + ks * 8 + lc    ]);
                a[mi][1] = __float_as_uint(As[(r + 8) * 36 + ks * 8 + lc    ]);
                a[mi][2] = __float_as_uint(As[(r    ) * 36 + ks * 8 + lc + 4]);
                a[mi][3] = __float_as_uint(As[(r + 8) * 36 + ks * 8 + lc + 4]);
            }
#pragma unroll
            for (int ni = 0; ni < 8; ni++) {
                int n = wn * 64 + ni * 8 + lr;
                b[ni][0] = __float_as_uint(Bs[n * 36 + ks * 8 + lc    ]);
                b[ni][1] = __float_as_uint(Bs[n * 36 + ks * 8 + lc + 4]);
            }
#pragma unroll
            for (int mi = 0; mi < 2; mi++)
#pragma unroll
                for (int ni = 0; ni < 8; ni++) {
                    asm volatile(
                        "mma.sync.aligned.m16n8k8.row.col.f32.tf32.tf32.f32 "
                        "{%0,%1,%2,%3}, {%4,%5,%6,%7}, {%8,%9}, {%0,%1,%2,%3};"
                        : "+f"(d[mi][ni][0]), "+f"(d[mi][ni][1]),
                          "+f"(d[mi][ni][2]), "+f"(d[mi][ni][3])
                        : "r"(a[mi][0]), "r"(a[mi][1]), "r"(a[mi][2]), "r"(a[mi][3]),
                          "r"(b[ni][0]), "r"(b[ni][1]));
                }
        }
    }

    // epilogue
#pragma unroll
    for (int mi = 0; mi < 2; mi++) {
#pragma unroll
        for (int half = 0; half < 2; half++) {
            int r = rowBase + wm * 32 + mi * 16 + lr + half * 8;
            if (r < ROWS) {
#pragma unroll
                for (int ni = 0; ni < 8; ni++) {
                    int c = wn * 64 + ni * 8 + lc * 2;
                    float p0 = d[mi][ni][half * 2 + 0] + bias[c];
                    float p1 = d[mi][ni][half * 2 + 1] + bias[c + 1];
                    size_t g = (size_t)r * 128 + c;
                    float v0, v1;
                    if (MODE == 0) {
                        v0 = p0; v1 = p1;
                    } else if (MODE == 1) {
                        v0 = 1.f / (1.f + __expf(-p0));
                        v1 = 1.f / (1.f + __expf(-p1));
                    } else if (MODE == 2) {
                        v0 = (1.f / (1.f + __expf(-p0))) * aux[g];
                        v1 = (1.f / (1.f + __expf(-p1))) * aux[g + 1];
                    } else {
                        float z0 = zbuf[g], z1 = zbuf[g + 1];
                        v0 = z0 * aux[g]     + (1.f - z0) * tanhf(p0);
                        v1 = z1 * aux[g + 1] + (1.f - z1) * tanhf(p1);
                    }
                    *(float2*)&out[g] = make_float2(v0, v1);
                }
            }
        }
    }
}

// all 6 projections (3 gates x {l,r}) in one launch: blockIdx.y = g*2+side
__global__ __launch_bounds__(256) void proj_all_kernel(
    const float* __restrict__ X, GateParams gp)
{
    int y = blockIdx.y;
    int g = y >> 1, side = y & 1;
    float* out = g_buf[side * 3 + g];
    gemm_core<1, 0>(X, nullptr, gp.W[y], gp.b[y], nullptr, nullptr, out);
}

// lin z (MODE1 -> Z=g_buf[9]) and lin r (MODE2 -> HR=g_buf[10]) fused
__global__ __launch_bounds__(256) void lin_zr_kernel(
    const float* __restrict__ H,
    const float* __restrict__ Wz, const float* __restrict__ bz,
    const float* __restrict__ Wr, const float* __restrict__ br)
{
    if (blockIdx.y == 0)
        gemm_core<2, 1>(g_buf[6], H, Wz, bz, H, nullptr, g_buf[9]);
    else
        gemm_core<2, 2>(g_buf[7], H, Wr, br, H, nullptr, g_buf[10]);
}

__global__ __launch_bounds__(256) void lin_h_kernel(
    const float* __restrict__ H,
    const float* __restrict__ W, const float* __restrict__ bias,
    float* __restrict__ out)
{
    gemm_core<2, 3>(g_buf[8], g_buf[10], W, bias, H, g_buf[9], out);
}

// ------------------------- warp-per-destination GATv2 aggregation (single-pass) -------------------------
// One warp = (gate, batch, dst). Lanes = features (4/lane). Each edge read ONCE:
// per-edge online softmax update (exact: softmax shift invariance).
__global__ __launch_bounds__(256) void gat_agg_kernel(AggParams ap)
{
    const int lane = threadIdx.x & 31;
    const int gw = blockIdx.x * 8 + (threadIdx.x >> 5);
    if (gw >= 3 * BB * NN) return;
    const int g = gw / (BB * NN);
    const int rem = gw - g * (BB * NN);
    const int b = rem / NN;
    const int d = rem - b * NN;

    const float* __restrict__ xlb = g_buf[g] + (size_t)b * NN * FD;   // xl rows for this batch
    const float* __restrict__ xr = g_buf[3 + g];
    float* __restrict__ Fout = g_buf[6 + g];
    const float* __restrict__ att = ap.att[g];
    const float* __restrict__ bias = ap.bias[g];

    const int start = g_rowptr[d];
    const int end   = g_rowptr[d + 1];
    const size_t nb = ((size_t)b * NN + d) * FD;

    float xr_v[4], at_v[4], acc[4];
#pragma unroll
    for (int q = 0; q < 4; q++) {
        xr_v[q] = xr[nb + lane + 32 * q];
        at_v[q] = att[lane + 32 * q];
        acc[q] = 0.f;
    }
    float m_run = -1e30f, denom = 0.f;

    for (int base = start; base < end; base += 32) {
        const int nv = min(32, end - base);
        int sidx = (base + lane < end) ? g_csrc[base + lane] : 0;
        for (int l = 0; l < nv; l++) {
            int s = __shfl_sync(0xffffffffu, sidx, l);
            const float* row = &xlb[(size_t)s * FD + lane];
            float r0 = row[0], r1 = row[32], r2 = row[64], r3 = row[96];
            // e = sum_f lrelu(xl + xr) * att   (lrelu(v) = max(v, 0.2v))
            float v0 = r0 + xr_v[0], v1 = r1 + xr_v[1];
            float v2 = r2 + xr_v[2], v3 = r3 + xr_v[3];
            float p = fmaxf(v0, 0.2f * v0) * at_v[0];
            p += fmaxf(v1, 0.2f * v1) * at_v[1];
            p += fmaxf(v2, 0.2f * v2) * at_v[2];
            p += fmaxf(v3, 0.2f * v3) * at_v[3];
#pragma unroll
            for (int o = 16; o > 0; o >>= 1)
                p += __shfl_xor_sync(0xffffffffu, p, o);
            // per-edge online softmax update (all lanes identical scalars)
            float m_new = fmaxf(m_run, p);
            float rs = __expf(m_run - m_new);   // 0 on first edge
            float wgt = __expf(p - m_new);
            denom = denom * rs + wgt;
            acc[0] = acc[0] * rs + wgt * r0;
            acc[1] = acc[1] * rs + wgt * r1;
            acc[2] = acc[2] * rs + wgt * r2;
            acc[3] = acc[3] * rs + wgt * r3;
            m_run = m_new;
        }
    }

    float inv = 1.f / denom;
#pragma unroll
    for (int q = 0; q < 4; q++) {
        float r = acc[q] * inv + bias[lane + 32 * q];
        Fout[nb + lane + 32 * q] = fmaxf(r, 0.f);
    }
}

// ------------------------- launch -------------------------
extern "C" void kernel_launch(void* const* d_in, const int* in_sizes, int n_in,
                              void* d_out, int out_size)
{
    (void)in_sizes; (void)n_in; (void)out_size;
    const float* X  = (const float*)d_in[0];
    const int*   EI = (const int*)d_in[1];   // int32 (JAX x64 disabled)
    const float* H  = (const float*)d_in[2];

    // per-gate params: Wl, bl, Wr, br, att, bias, Wlin, blin  (z@3, r@11, h@19)
    const float* p[24];
    for (int i = 0; i < 24; i++) p[i] = (const float*)d_in[3 + i];
    const float **gz = p, **gr = p + 8, **gh = p + 16;

    // idempotent, host-side, executes immediately (not captured)
    cudaFuncSetAttribute(proj_all_kernel, cudaFuncAttributeMaxDynamicSharedMemorySize, GEMM_SMEM_BYTES);
    cudaFuncSetAttribute(lin_zr_kernel,   cudaFuncAttributeMaxDynamicSharedMemorySize, GEMM_SMEM_BYTES);
    cudaFuncSetAttribute(lin_h_kernel,    cudaFuncAttributeMaxDynamicSharedMemorySize, GEMM_SMEM_BYTES);

    // CSR build (once; shared by all gates)
    init_deg_kernel<<<(NN + 255) / 256, 256>>>();
    count_deg_kernel<<<(MM + 255) / 256, 256>>>(EI);
    scan_kernel<<<1, 1024>>>();
    scatter_csr_kernel<<<(MM + 255) / 256, 256>>>(EI);

    const int GB = (ROWS + 127) / 128;   // 313

    GateParams gp;
    for (int g = 0; g < 3; g++) {
        gp.W[g * 2 + 0] = p[g * 8 + 0]; gp.b[g * 2 + 0] = p[g * 8 + 1];
        gp.W[g * 2 + 1] = p[g * 8 + 2]; gp.b[g * 2 + 1] = p[g * 8 + 3];
    }
    AggParams ap;
    ap.att[0] = gz[4]; ap.bias[0] = gz[5];
    ap.att[1] = gr[4]; ap.bias[1] = gr[5];
    ap.att[2] = gh[4]; ap.bias[2] = gh[5];

    dim3 projGrid(GB, 6);
    proj_all_kernel<<<projGrid, 256, GEMM_SMEM_BYTES>>>(X, gp);

    int nwarps = 3 * BB * NN;
    gat_agg_kernel<<<(nwarps + 7) / 8, 256>>>(ap);

    dim3 linGrid(GB, 2);
    lin_zr_kernel<<<linGrid, 256, GEMM_SMEM_BYTES>>>(H, gz[6], gz[7], gr[6], gr[7]);
    lin_h_kernel<<<GB, 256, GEMM_SMEM_BYTES>>>(H, gh[6], gh[7], (float*)d_out);
}

// round 15
// speedup vs baseline: 4.3323x; 1.1903x over previous
#include <cuda_runtime.h>
#include <cuda_fp16.h>
#include <math.h>
#include <stdint.h>

#define NN 10000
#define EE 160000
#define MM (EE + NN)   // 170000 edges incl self loops
#define FD 128
#define BB 4
#define ROWS (BB * NN) // 40000

// ------------------------- scratch (device globals; no allocation) -------------------------
// fp32 slots: 0-2 xl[g], 3-5 xr[g], 9 Z
__device__ float g_buf[10][(size_t)ROWS * FD];
__device__ int   g_deg[NN];
__device__ int   g_rowptr[NN + 1];
__device__ int   g_cursor[NN];
__device__ int   g_csrc[MM];
// fp16 planes for HMMA GEMMs
__device__ __half g_xh[(size_t)ROWS * FD];       // X
__device__ __half g_hh[(size_t)ROWS * FD];       // H
__device__ __half g_fh[3][(size_t)ROWS * FD];    // F per gate (agg output)
__device__ __half g_hrh[(size_t)ROWS * FD];      // H*R
__device__ __half g_wph[6][FD * FD];             // proj weights (Wl/Wr x 3)
__device__ __half g_wlh[3][FD * 2 * FD];         // lin weights

struct GateParams {
    const float* W[6];   // y = g*2+side
    const float* b[6];
};
struct LinW { const float* W[3]; };
struct AggParams {
    const float* att[3];
    const float* bias[3];
};

// ------------------------- CSR build -------------------------
__global__ void init_deg_kernel() {
    int i = blockIdx.x * 256 + threadIdx.x;
    if (i < NN) g_deg[i] = 0;
}

__global__ void count_deg_kernel(const int* __restrict__ ei) {
    int m = blockIdx.x * 256 + threadIdx.x;
    if (m >= MM) return;
    int d = (m < EE) ? ei[EE + m] : (m - EE);
    if ((unsigned)d < NN) atomicAdd(&g_deg[d], 1);
}

__global__ void scan_kernel() {
    __shared__ int part[1024];
    int tid = threadIdx.x;
    const int CH = 10;
    int base = tid * CH;
    int loc[CH];
    int s = 0;
#pragma unroll
    for (int i = 0; i < CH; i++) {
        int v = (base + i < NN) ? g_deg[base + i] : 0;
        loc[i] = s; s += v;
    }
    part[tid] = s;
    __syncthreads();
    for (int off = 1; off < 1024; off <<= 1) {
        int add = (tid >= off) ? part[tid - off] : 0;
        __syncthreads();
        part[tid] += add;
        __syncthreads();
    }
    int pre = (tid > 0) ? part[tid - 1] : 0;
#pragma unroll
    for (int i = 0; i < CH; i++) {
        if (base + i < NN) {
            int r = pre + loc[i];
            g_rowptr[base + i] = r;
            g_cursor[base + i] = r;
        }
    }
    if (tid == 1023) g_rowptr[NN] = part[1023];
}

__global__ void scatter_csr_kernel(const int* __restrict__ ei) {
    int m = blockIdx.x * 256 + threadIdx.x;
    if (m >= MM) return;
    int s, d;
    if (m < EE) { s = ei[m]; d = ei[EE + m]; }
    else        { s = d = m - EE; }
    if ((unsigned)d >= NN || (unsigned)s >= NN) return;
    int pos = atomicAdd(&g_cursor[d], 1);
    if (pos < MM) g_csrc[pos] = s;
}

// ------------------------- fp16 conversions -------------------------
__global__ void conv_xh_kernel(const float* __restrict__ X, const float* __restrict__ H) {
    int i = blockIdx.x * 256 + threadIdx.x;
    if (i >= ROWS * FD / 4) return;
    float4 vx = ((const float4*)X)[i];
    float4 vh = ((const float4*)H)[i];
    ((__half2*)g_xh)[i * 2 + 0] = __floats2half2_rn(vx.x, vx.y);
    ((__half2*)g_xh)[i * 2 + 1] = __floats2half2_rn(vx.z, vx.w);
    ((__half2*)g_hh)[i * 2 + 0] = __floats2half2_rn(vh.x, vh.y);
    ((__half2*)g_hh)[i * 2 + 1] = __floats2half2_rn(vh.z, vh.w);
}

// y 0..5: proj weights (16384 floats), y 6..8: lin weights (32768 floats)
__global__ void conv_w_kernel(GateParams gp, LinW lw) {
    int y = blockIdx.y;
    int n = (y < 6) ? (FD * FD) : (FD * 2 * FD);
    const float* src = (y < 6) ? gp.W[y] : lw.W[y - 6];
    __half* dst = (y < 6) ? g_wph[y] : g_wlh[y - 6];
    int i = blockIdx.x * 256 + threadIdx.x;
    if (i >= n / 4) return;
    float4 v = ((const float4*)src)[i];
    ((__half2*)dst)[i * 2 + 0] = __floats2half2_rn(v.x, v.y);
    ((__half2*)dst)[i * 2 + 1] = __floats2half2_rn(v.z, v.w);
}

// ------------------------- fp16 HMMA GEMM (cp.async 4-stage ring) -------------------------
// C[r,o] = sum_f A(f) * W[o,f] (+bias, fused epilogue), fp16 inputs, fp32 accum.
// Block tile 128x128, 256 threads (8 warps: 4m x 2n), warp tile m32 x n64, mma m16n8k16.
// Tiles staged untransposed in 32-k chunks: row stride 40 halves (pad 8) ->
// fragment word = row*20 + ks*8 + lc (+4); banks (20*lr+lc)%32 all distinct.
#define HSTR 40                                // halves per row incl pad
#define TILE_HH (128 * HSTR)                   // halves per tile (10240B)
#define GEMM_SMEM_BYTES (4 * 2 * TILE_HH * 2)  // 4 stages x (A+B) = 81920B

__device__ __forceinline__ void cp_async16h(__half* s, const __half* g) {
    uint32_t sa = (uint32_t)__cvta_generic_to_shared(s);
    asm volatile("cp.async.cg.shared.global [%0], [%1], 16;" :: "r"(sa), "l"(g));
}
__device__ __forceinline__ void cp_commit() {
    asm volatile("cp.async.commit_group;");
}
__device__ __forceinline__ void cp_wait(int n) {
    if (n == 2)      asm volatile("cp.async.wait_group 2;");
    else if (n == 1) asm volatile("cp.async.wait_group 1;");
    else             asm volatile("cp.async.wait_group 0;");
}

// MODE 0: out=pre (fp32)            -> proj (xl/xr)
// MODE 1: out=sigmoid(pre) (fp32)   -> Z
// MODE 2: outH=half(sigmoid(pre)*aux)  -> HR (fp16)
// MODE 3: out=zbuf*aux+(1-zbuf)*tanh(pre) (fp32) -> final
template<int NPH, int MODE>
__device__ __forceinline__ void gemm_core_h(
    const __half* __restrict__ A1, const __half* __restrict__ A2,
    const __half* __restrict__ W,  const float* __restrict__ bias,
    const float* __restrict__ aux, const float* __restrict__ zbuf,
    float* __restrict__ outF, __half* __restrict__ outH)
{
    extern __shared__ __half dynsmh[];

    const int tid  = threadIdx.x;
    const int lane = tid & 31;
    const int w    = tid >> 5;
    const int wm   = w & 3;
    const int wn   = w >> 2;
    const int lr   = lane >> 2;
    const int lc   = lane & 3;
    const int rowBase = blockIdx.x * 128;
    const int KW = NPH * 128;
    const int NC = NPH * 4;

    float d[2][8][4];
#pragma unroll
    for (int mi = 0; mi < 2; mi++)
#pragma unroll
        for (int ni = 0; ni < 8; ni++)
#pragma unroll
            for (int q = 0; q < 4; q++) d[mi][ni][q] = 0.f;

    auto issue = [&](int c, int buf) {
        const __half* A = (c >= 4) ? A2 : A1;
        const int kc = c & 3;
        __half* As = dynsmh + buf * 2 * TILE_HH;
        __half* Bs = As + TILE_HH;
#pragma unroll
        for (int i = 0; i < 2; i++) {
            int idx = tid + i * 256;
            int row = idx >> 2, kg = idx & 3;         // 128 rows x 4 x 16B
            int gr = rowBase + row;
            if (gr >= ROWS) gr = ROWS - 1;
            cp_async16h(&As[row * HSTR + kg * 8], A + (size_t)gr * 128 + kc * 32 + kg * 8);
        }
#pragma unroll
        for (int i = 0; i < 2; i++) {
            int idx = tid + i * 256;
            int n = idx >> 2, kg = idx & 3;
            cp_async16h(&Bs[n * HSTR + kg * 8], W + (size_t)n * KW + (c >> 2) * 128 + kc * 32 + kg * 8);
        }
        cp_commit();
    };

    issue(0, 0);
    if (NC > 1) issue(1, 1);
    if (NC > 2) issue(2, 2);

    for (int c = 0; c < NC; c++) {
        int rem = NC - 1 - c;
        cp_wait(rem < 2 ? rem : 2);
        __syncthreads();
        if (c + 3 < NC) issue(c + 3, (c + 3) & 3);

        const uint32_t* AsW = (const uint32_t*)(dynsmh + (c & 3) * 2 * TILE_HH);
        const uint32_t* BsW = AsW + TILE_HH / 2;
#pragma unroll
        for (int ks = 0; ks < 2; ks++) {           // two k16 steps per 32-k chunk
            uint32_t a[2][4], b[8][2];
#pragma unroll
            for (int mi = 0; mi < 2; mi++) {
                int r = wm * 32 + mi * 16 + lr;
                int base0 = r * 20 + ks * 8 + lc;
                a[mi][0] = AsW[base0];
                a[mi][1] = AsW[base0 + 8 * 20];
                a[mi][2] = AsW[base0 + 4];
                a[mi][3] = AsW[base0 + 8 * 20 + 4];
            }
#pragma unroll
            for (int ni = 0; ni < 8; ni++) {
                int n = wn * 64 + ni * 8 + lr;
                int base0 = n * 20 + ks * 8 + lc;
                b[ni][0] = BsW[base0];
                b[ni][1] = BsW[base0 + 4];
            }
#pragma unroll
            for (int mi = 0; mi < 2; mi++)
#pragma unroll
                for (int ni = 0; ni < 8; ni++) {
                    asm volatile(
                        "mma.sync.aligned.m16n8k16.row.col.f32.f16.f16.f32 "
                        "{%0,%1,%2,%3}, {%4,%5,%6,%7}, {%8,%9}, {%0,%1,%2,%3};"
                        : "+f"(d[mi][ni][0]), "+f"(d[mi][ni][1]),
                          "+f"(d[mi][ni][2]), "+f"(d[mi][ni][3])
                        : "r"(a[mi][0]), "r"(a[mi][1]), "r"(a[mi][2]), "r"(a[mi][3]),
                          "r"(b[ni][0]), "r"(b[ni][1]));
                }
        }
    }

    // epilogue
#pragma unroll
    for (int mi = 0; mi < 2; mi++) {
#pragma unroll
        for (int half = 0; half < 2; half++) {
            int r = rowBase + wm * 32 + mi * 16 + lr + half * 8;
            if (r < ROWS) {
#pragma unroll
                for (int ni = 0; ni < 8; ni++) {
                    int c = wn * 64 + ni * 8 + lc * 2;
                    float p0 = d[mi][ni][half * 2 + 0] + bias[c];
                    float p1 = d[mi][ni][half * 2 + 1] + bias[c + 1];
                    size_t g = (size_t)r * 128 + c;
                    if (MODE == 0) {
                        *(float2*)&outF[g] = make_float2(p0, p1);
                    } else if (MODE == 1) {
                        *(float2*)&outF[g] = make_float2(1.f / (1.f + __expf(-p0)),
                                                         1.f / (1.f + __expf(-p1)));
                    } else if (MODE == 2) {
                        float v0 = (1.f / (1.f + __expf(-p0))) * aux[g];
                        float v1 = (1.f / (1.f + __expf(-p1))) * aux[g + 1];
                        *(__half2*)&outH[g] = __floats2half2_rn(v0, v1);
                    } else {
                        float z0 = zbuf[g], z1 = zbuf[g + 1];
                        float v0 = z0 * aux[g]     + (1.f - z0) * tanhf(p0);
                        float v1 = z1 * aux[g + 1] + (1.f - z1) * tanhf(p1);
                        *(float2*)&outF[g] = make_float2(v0, v1);
                    }
                }
            }
        }
    }
}

// all 6 projections in one launch: blockIdx.y = g*2+side
__global__ __launch_bounds__(256) void proj_all_kernel(GateParams gp)
{
    int y = blockIdx.y;
    int g = y >> 1, side = y & 1;
    gemm_core_h<1, 0>(g_xh, nullptr, g_wph[y], gp.b[y], nullptr, nullptr,
                      g_buf[side * 3 + g], nullptr);
}

// lin z (MODE1 -> Z fp32) and lin r (MODE2 -> HR fp16) fused
__global__ __launch_bounds__(256) void lin_zr_kernel(
    const float* __restrict__ H,
    const float* __restrict__ bz, const float* __restrict__ br)
{
    if (blockIdx.y == 0)
        gemm_core_h<2, 1>(g_fh[0], g_hh, g_wlh[0], bz, H, nullptr, g_buf[9], nullptr);
    else
        gemm_core_h<2, 2>(g_fh[1], g_hh, g_wlh[1], br, H, nullptr, nullptr, g_hrh);
}

__global__ __launch_bounds__(256) void lin_h_kernel(
    const float* __restrict__ H, const float* __restrict__ bias,
    float* __restrict__ out)
{
    gemm_core_h<2, 3>(g_fh[2], g_hrh, g_wlh[2], bias, H, g_buf[9], out, nullptr);
}

// ------------------------- warp-per-destination GATv2 aggregation (single-pass) -------------------------
__global__ __launch_bounds__(256) void gat_agg_kernel(AggParams ap)
{
    const int lane = threadIdx.x & 31;
    const int gw = blockIdx.x * 8 + (threadIdx.x >> 5);
    if (gw >= 3 * BB * NN) return;
    const int g = gw / (BB * NN);
    const int rem = gw - g * (BB * NN);
    const int b = rem / NN;
    const int d = rem - b * NN;

    const float* __restrict__ xlb = g_buf[g] + (size_t)b * NN * FD;
    const float* __restrict__ xr = g_buf[3 + g];
    __half* __restrict__ Fout = g_fh[g];
    const float* __restrict__ att = ap.att[g];
    const float* __restrict__ bias = ap.bias[g];

    const int start = g_rowptr[d];
    const int end   = g_rowptr[d + 1];
    const size_t nb = ((size_t)b * NN + d) * FD;

    float xr_v[4], at_v[4], acc[4];
#pragma unroll
    for (int q = 0; q < 4; q++) {
        xr_v[q] = xr[nb + lane + 32 * q];
        at_v[q] = att[lane + 32 * q];
        acc[q] = 0.f;
    }
    float m_run = -1e30f, denom = 0.f;

    for (int base = start; base < end; base += 32) {
        const int nv = min(32, end - base);
        int sidx = (base + lane < end) ? g_csrc[base + lane] : 0;
        for (int l = 0; l < nv; l++) {
            int s = __shfl_sync(0xffffffffu, sidx, l);
            const float* row = &xlb[(size_t)s * FD + lane];
            float r0 = row[0], r1 = row[32], r2 = row[64], r3 = row[96];
            float v0 = r0 + xr_v[0], v1 = r1 + xr_v[1];
            float v2 = r2 + xr_v[2], v3 = r3 + xr_v[3];
            float p = fmaxf(v0, 0.2f * v0) * at_v[0];
            p += fmaxf(v1, 0.2f * v1) * at_v[1];
            p += fmaxf(v2, 0.2f * v2) * at_v[2];
            p += fmaxf(v3, 0.2f * v3) * at_v[3];
#pragma unroll
            for (int o = 16; o > 0; o >>= 1)
                p += __shfl_xor_sync(0xffffffffu, p, o);
            float m_new = fmaxf(m_run, p);
            float rs = __expf(m_run - m_new);
            float wgt = __expf(p - m_new);
            denom = denom * rs + wgt;
            acc[0] = acc[0] * rs + wgt * r0;
            acc[1] = acc[1] * rs + wgt * r1;
            acc[2] = acc[2] * rs + wgt * r2;
            acc[3] = acc[3] * rs + wgt * r3;
            m_run = m_new;
        }
    }

    float inv = 1.f / denom;
#pragma unroll
    for (int q = 0; q < 4; q++) {
        float r = acc[q] * inv + bias[lane + 32 * q];
        Fout[nb + lane + 32 * q] = __float2half(fmaxf(r, 0.f));
    }
}

// ------------------------- launch -------------------------
extern "C" void kernel_launch(void* const* d_in, const int* in_sizes, int n_in,
                              void* d_out, int out_size)
{
    (void)in_sizes; (void)n_in; (void)out_size;
    const float* X  = (const float*)d_in[0];
    const int*   EI = (const int*)d_in[1];   // int32 (JAX x64 disabled)
    const float* H  = (const float*)d_in[2];

    // per-gate params: Wl, bl, Wr, br, att, bias, Wlin, blin  (z@3, r@11, h@19)
    const float* p[24];
    for (int i = 0; i < 24; i++) p[i] = (const float*)d_in[3 + i];
    const float **gz = p, **gr = p + 8, **gh = p + 16;

    cudaFuncSetAttribute(proj_all_kernel, cudaFuncAttributeMaxDynamicSharedMemorySize, GEMM_SMEM_BYTES);
    cudaFuncSetAttribute(lin_zr_kernel,   cudaFuncAttributeMaxDynamicSharedMemorySize, GEMM_SMEM_BYTES);
    cudaFuncSetAttribute(lin_h_kernel,    cudaFuncAttributeMaxDynamicSharedMemorySize, GEMM_SMEM_BYTES);

    GateParams gp;
    for (int g = 0; g < 3; g++) {
        gp.W[g * 2 + 0] = p[g * 8 + 0]; gp.b[g * 2 + 0] = p[g * 8 + 1];
        gp.W[g * 2 + 1] = p[g * 8 + 2]; gp.b[g * 2 + 1] = p[g * 8 + 3];
    }
    LinW lw;
    lw.W[0] = gz[6]; lw.W[1] = gr[6]; lw.W[2] = gh[6];
    AggParams ap;
    ap.att[0] = gz[4]; ap.bias[0] = gz[5];
    ap.att[1] = gr[4]; ap.bias[1] = gr[5];
    ap.att[2] = gh[4]; ap.bias[2] = gh[5];

    // conversions + CSR build
    conv_xh_kernel<<<(ROWS * FD / 4 + 255) / 256, 256>>>(X, H);
    conv_w_kernel<<<dim3(32, 9), 256>>>(gp, lw);   // 32 blocks covers 32768/4 elems
    init_deg_kernel<<<(NN + 255) / 256, 256>>>();
    count_deg_kernel<<<(MM + 255) / 256, 256>>>(EI);
    scan_kernel<<<1, 1024>>>();
    scatter_csr_kernel<<<(MM + 255) / 256, 256>>>(EI);

    const int GB = (ROWS + 127) / 128;   // 313

    // 6 projections (fp16 HMMA)
    dim3 projGrid(GB, 6);
    proj_all_kernel<<<projGrid, 256, GEMM_SMEM_BYTES>>>(gp);

    // aggregation (all 3 gates) -> F fp16
    int nwarps = 3 * BB * NN;
    gat_agg_kernel<<<(nwarps + 7) / 8, 256>>>(ap);

    // gate linears
    dim3 linGrid(GB, 2);
    lin_zr_kernel<<<linGrid, 256, GEMM_SMEM_BYTES>>>(H, gz[7], gr[7]);
    lin_h_kernel<<<GB, 256, GEMM_SMEM_BYTES>>>(H, gh[7], (float*)d_out);
}